// round 6
// baseline (speedup 1.0000x reference)
#include <cuda_runtime.h>
#include <cuda_bf16.h>
#include <math.h>

// ---------------------------------------------------------------------------
// B=4, T=2048, P=16, J=256, H=4, D=16, MEM=64, K_OUT=192
// N = B*P = 64 sequences; tokens M_TOK = 131072
// gemmA (tf32 tensor) now fuses the LN(q)/LN+L2(k)/v epilogue.
// beta/alpha: slim warp-per-token kernel. Scan: chunked, f32x2-packed math.
// ---------------------------------------------------------------------------

#define M_TOK   131072
#define JDIM    256
#define NPRE    192
#define NSEQ    64
#define TLEN    2048
#define HEADS   4
#define DHEAD   16
#define KOUT    192
#define CCH     64
#define NCHUNK  (TLEN / CCH)

typedef unsigned long long u64;

// -------- scratch (device globals; no allocation allowed) --------
__device__ float g_Bpack [(size_t)JDIM * NPRE];
__device__ float g_Bpack2[(size_t)64 * KOUT];
__device__ float g_q     [(size_t)M_TOK * 64];
__device__ float g_k     [(size_t)M_TOK * 64];
__device__ float g_v     [(size_t)M_TOK * 64];
__device__ float g_beta  [(size_t)M_TOK * HEADS];
__device__ float g_alpha [(size_t)M_TOK * HEADS];
__device__ float g_o     [(size_t)M_TOK * 64];
__device__ float g_T [(size_t)NSEQ * NCHUNK * HEADS * 256];
__device__ float g_U [(size_t)NSEQ * NCHUNK * HEADS * 256];
__device__ float g_S [(size_t)NSEQ * NCHUNK * HEADS * 256];

// ---- tf32 / packed-f32x2 helpers ----
__device__ __forceinline__ float tf32r(float x)
{
    unsigned u;
    asm("cvt.rna.tf32.f32 %0, %1;" : "=r"(u) : "f"(x));
    return __uint_as_float(u);
}
__device__ __forceinline__ unsigned fu(float x) { return __float_as_uint(x); }

__device__ __forceinline__ u64 pk2(float lo, float hi)
{
    u64 r;
    asm("mov.b64 %0, {%1, %2};" : "=l"(r) : "f"(lo), "f"(hi));
    return r;
}
__device__ __forceinline__ void upk2(u64 v, float& lo, float& hi)
{
    asm("mov.b64 {%0, %1}, %2;" : "=f"(lo), "=f"(hi) : "l"(v));
}
__device__ __forceinline__ u64 ffma2(u64 a, u64 b, u64 c)
{
    u64 d;
    asm("fma.rn.f32x2 %0, %1, %2, %3;" : "=l"(d) : "l"(a), "l"(b), "l"(c));
    return d;
}

#define MMA_TF32(c, a, b)                                                     \
    asm volatile("mma.sync.aligned.m16n8k8.row.col.f32.tf32.tf32.f32 "        \
                 "{%0,%1,%2,%3}, {%4,%5,%6,%7}, {%8,%9}, {%0,%1,%2,%3};"      \
                 : "+f"((c)[0]), "+f"((c)[1]), "+f"((c)[2]), "+f"((c)[3])     \
                 : "r"((a)[0]), "r"((a)[1]), "r"((a)[2]), "r"((a)[3]),        \
                   "r"((b)[0]), "r"((b)[1]))

// ---------------------------------------------------------------------------
// Kernel 0: pack weights (k-major) + round to tf32
// ---------------------------------------------------------------------------
__global__ void pack_kernel(const float* __restrict__ Wq,
                            const float* __restrict__ Wk,
                            const float* __restrict__ Wv,
                            const float* __restrict__ out_w)
{
    int idx = blockIdx.x * blockDim.x + threadIdx.x;
    if (idx < JDIM * NPRE) {
        int k = idx / NPRE;
        int o = idx - k * NPRE;
        float val;
        if      (o < 64)  val = Wq[(size_t)o       * JDIM + k];
        else if (o < 128) val = Wk[(size_t)(o-64)  * JDIM + k];
        else              val = Wv[(size_t)(o-128) * JDIM + k];
        g_Bpack[idx] = tf32r(val);
    }
    int idx2 = idx - JDIM * NPRE;
    if (idx2 >= 0 && idx2 < 64 * KOUT) {
        int k = idx2 / KOUT;
        int o = idx2 - k * KOUT;
        g_Bpack2[idx2] = tf32r(out_w[(size_t)o * 64 + k]);
    }
}

// ---------------------------------------------------------------------------
// warp reduction helpers
// ---------------------------------------------------------------------------
__device__ __forceinline__ float red16(float x)
{
    x += __shfl_xor_sync(0xffffffffu, x, 8);
    x += __shfl_xor_sync(0xffffffffu, x, 4);
    x += __shfl_xor_sync(0xffffffffu, x, 2);
    x += __shfl_xor_sync(0xffffffffu, x, 1);
    return x;
}
__device__ __forceinline__ float red32(float x)
{
    x += __shfl_xor_sync(0xffffffffu, x, 16);
    x += __shfl_xor_sync(0xffffffffu, x, 8);
    x += __shfl_xor_sync(0xffffffffu, x, 4);
    x += __shfl_xor_sync(0xffffffffu, x, 2);
    x += __shfl_xor_sync(0xffffffffu, x, 1);
    return x;
}
__device__ __forceinline__ float sigm(float x) { return 1.f / (1.f + expf(-x)); }

// ---------------------------------------------------------------------------
// Kernel A (tf32 tensor + fused epilogue):
//   pre[128,64] = x_tile @ Wsec ; bx=0 -> LN -> g_q, bx=1 -> LN+L2 -> g_k,
//   bx=2 -> g_v direct. BM=128, BN=64, BK=32, 128 threads (4 warps, 2x2).
// ---------------------------------------------------------------------------
#define ASTR 36
#define BSTR 68

__global__ __launch_bounds__(128) void gemmA_kernel(
    const float* __restrict__ A,
    const float* __restrict__ lqw, const float* __restrict__ lqb,
    const float* __restrict__ lkw, const float* __restrict__ lkb)
{
    __shared__ __align__(16) float buf[128 * 68];   // 34.8 KB, multi-purpose
    float* As = buf;               // [128][ASTR] during mainloop
    float* Bs = buf + 128 * ASTR;  // [32][BSTR]
    float* Cs = buf;               // [128][65] after mainloop

    const int tid  = threadIdx.x;
    const int lane = tid & 31;
    const int wid  = tid >> 5;
    const int g    = lane >> 2;
    const int t    = lane & 3;
    const int wm   = (wid >> 1) * 64;
    const int wn   = (wid & 1) * 32;
    const int bx   = blockIdx.x;          // 0=q, 1=k, 2=v
    const int m0   = blockIdx.y * 128;
    const int n0   = bx * 64;

    float acc[4][4][4];
#pragma unroll
    for (int i = 0; i < 4; i++)
#pragma unroll
        for (int j = 0; j < 4; j++)
#pragma unroll
            for (int r = 0; r < 4; r++) acc[i][j][r] = 0.f;

    for (int k0 = 0; k0 < JDIM; k0 += 32) {
#pragma unroll
        for (int i = 0; i < 8; i++) {
            int e   = i * 128 + tid;
            int row = e >> 3;
            int cq  = (e & 7) * 4;
            float4 av = *(const float4*)(A + (size_t)(m0 + row) * JDIM + k0 + cq);
            float4 tv = make_float4(tf32r(av.x), tf32r(av.y), tf32r(av.z), tf32r(av.w));
            *(float4*)&As[row * ASTR + cq] = tv;
        }
#pragma unroll
        for (int i = 0; i < 4; i++) {
            int e  = i * 128 + tid;
            int kk = e >> 4;
            int cq = (e & 15) * 4;
            float4 bv = *(const float4*)(g_Bpack + (size_t)(k0 + kk) * NPRE + n0 + cq);
            *(float4*)&Bs[kk * BSTR + cq] = bv;
        }
        __syncthreads();

#pragma unroll
        for (int ks = 0; ks < 4; ks++) {
            const int kb = ks * 8;
            unsigned a[4][4], b[4][2];
#pragma unroll
            for (int mt = 0; mt < 4; mt++) {
                int r = wm + mt * 16 + g;
                a[mt][0] = fu(As[r * ASTR + kb + t]);
                a[mt][1] = fu(As[(r + 8) * ASTR + kb + t]);
                a[mt][2] = fu(As[r * ASTR + kb + t + 4]);
                a[mt][3] = fu(As[(r + 8) * ASTR + kb + t + 4]);
            }
#pragma unroll
            for (int nt = 0; nt < 4; nt++) {
                int n = wn + nt * 8 + g;
                b[nt][0] = fu(Bs[(kb + t) * BSTR + n]);
                b[nt][1] = fu(Bs[(kb + t + 4) * BSTR + n]);
            }
#pragma unroll
            for (int mt = 0; mt < 4; mt++)
#pragma unroll
                for (int nt = 0; nt < 4; nt++)
                    MMA_TF32(acc[mt][nt], a[mt], b[nt]);
        }
        __syncthreads();
    }

    if (bx == 2) {
        // v: store accumulators straight to g_v [row][col] (stride 64)
#pragma unroll
        for (int mt = 0; mt < 4; mt++) {
#pragma unroll
            for (int nt = 0; nt < 4; nt++) {
                int row = m0 + wm + mt * 16 + g;
                int col = wn + nt * 8 + 2 * t;
                *(float2*)(g_v + (size_t)row * 64 + col) =
                    make_float2(acc[mt][nt][0], acc[mt][nt][1]);
                *(float2*)(g_v + (size_t)(row + 8) * 64 + col) =
                    make_float2(acc[mt][nt][2], acc[mt][nt][3]);
            }
        }
        return;
    }

    // q/k: stage 128x64 results into smem, apply LN (+L2 for k), store.
#pragma unroll
    for (int mt = 0; mt < 4; mt++) {
#pragma unroll
        for (int nt = 0; nt < 4; nt++) {
            int r   = wm + mt * 16 + g;
            int col = wn + nt * 8 + 2 * t;
            Cs[r * 65 + col]           = acc[mt][nt][0];
            Cs[r * 65 + col + 1]       = acc[mt][nt][1];
            Cs[(r + 8) * 65 + col]     = acc[mt][nt][2];
            Cs[(r + 8) * 65 + col + 1] = acc[mt][nt][3];
        }
    }
    __syncthreads();

    const int   di    = lane & 15;
    const float ww    = (bx == 0) ? lqw[di] : lkw[di];
    const float wb    = (bx == 0) ? lqb[di] : lkb[di];
    float*      dst   = (bx == 0) ? g_q : g_k;
    const float inv16 = 1.f / 16.f;

    for (int rr = 0; rr < 32; rr++) {
        int row = wid * 32 + rr;
        float v0 = Cs[row * 65 + lane];
        float v1 = Cs[row * 65 + 32 + lane];
        float mu0 = red16(v0) * inv16, mu1 = red16(v1) * inv16;
        float d0 = v0 - mu0, d1 = v1 - mu1;
        float va0 = red16(d0 * d0) * inv16, va1 = red16(d1 * d1) * inv16;
        float n0v = d0 / sqrtf(va0 + 1e-5f) * ww + wb;
        float n1v = d1 / sqrtf(va1 + 1e-5f) * ww + wb;
        if (bx == 1) {
            float s0 = red16(n0v * n0v);
            float s1 = red16(n1v * n1v);
            n0v = n0v / fmaxf(sqrtf(s0), 1e-12f);
            n1v = n1v / fmaxf(sqrtf(s1), 1e-12f);
        }
        size_t gm = (size_t)(m0 + row) * 64;
        dst[gm + lane]      = n0v;
        dst[gm + 32 + lane] = n1v;
    }
}

// ---------------------------------------------------------------------------
// Kernel B: beta/alpha only (warp per token)
// ---------------------------------------------------------------------------
__global__ __launch_bounds__(256) void beta_kernel(
    const float* __restrict__ x,
    const float* __restrict__ curv, const float* __restrict__ ent,
    const float* __restrict__ Wbw,  const float* __restrict__ Wbb,
    const float* __restrict__ Waw,  const float* __restrict__ Wab,
    const float* __restrict__ cw,   const float* __restrict__ ew)
{
    const int tid  = threadIdx.x;
    const int lane = tid & 31;
    const int w    = tid >> 5;
    const size_t m = (size_t)blockIdx.x * 8 + w;

    const float4* x4 = (const float4*)(x + m * JDIM);
    float4 xv0 = x4[lane * 2];
    float4 xv1 = x4[lane * 2 + 1];
    float par[8];
#pragma unroll
    for (int hh = 0; hh < 8; hh++) {
        const float* wr = (hh < 4) ? (Wbw + (size_t)hh * JDIM)
                                   : (Waw + (size_t)(hh - 4) * JDIM);
        float4 w0 = ((const float4*)wr)[lane * 2];
        float4 w1 = ((const float4*)wr)[lane * 2 + 1];
        float s = xv0.x * w0.x + xv0.y * w0.y + xv0.z * w0.z + xv0.w * w0.w
                + xv1.x * w1.x + xv1.y * w1.y + xv1.z * w1.z + xv1.w * w1.w;
        par[hh] = red32(s);
    }
    if (lane < HEADS) {
        int nidx = (int)(m >> 11);
        int bidx = nidx >> 4;
        float Kv = fminf(fabsf(curv[bidx]), 10.f);
        float Sv = fminf(fmaxf(ent[bidx], 0.f), 5.f);
        float b1 = sigm(par[lane] + Wbb[lane]);
        g_beta[m * HEADS + lane]  = sigm(b1 + Kv * cw[lane]);
        float a1 = sigm(par[4 + lane] + Wab[lane]);
        g_alpha[m * HEADS + lane] = sigm(a1 + Sv * ew[lane]);
    }
}

// ---------------------------------------------------------------------------
// Scan pass 1 (f32x2-packed): build T = prod A_t, U = sum B_t prod A_s.
// ---------------------------------------------------------------------------
__global__ __launch_bounds__(64) void scan_phase1()
{
    const int n   = blockIdx.x;
    const int c   = blockIdx.y;
    const int tid = threadIdx.x;
    const int h   = tid >> 4;
    const int i   = tid & 15;

    __shared__ __align__(16) float ks[CCH * 64];
    __shared__ __align__(16) float vs[CCH * 64];
    __shared__ float bs[CCH * HEADS];
    __shared__ float as_[CCH * HEADS];

    const size_t base  = ((size_t)n * TLEN + (size_t)c * CCH) * 64;
    const size_t base2 = ((size_t)n * TLEN + (size_t)c * CCH) * HEADS;
    {
        const float4* gk4 = (const float4*)(g_k + base);
        const float4* gv4 = (const float4*)(g_v + base);
#pragma unroll
        for (int idx = tid; idx < CCH * 16; idx += 64) {
            ((float4*)ks)[idx] = gk4[idx];
            ((float4*)vs)[idx] = gv4[idx];
        }
#pragma unroll
        for (int idx = tid; idx < CCH * HEADS; idx += 64) {
            bs[idx]  = g_beta[base2 + idx];
            as_[idx] = g_alpha[base2 + idx];
        }
    }
    __syncthreads();

    u64 T2[8], U2[8];
#pragma unroll
    for (int p = 0; p < 8; p++) {
        T2[p] = pk2((2 * p == i) ? 1.f : 0.f, (2 * p + 1 == i) ? 1.f : 0.f);
        U2[p] = 0ull;
    }

    for (int tt = 0; tt < CCH; tt++) {
        const u64* kp2 = (const u64*)(ks + tt * 64 + h * 16);
        u64 k2[8];
#pragma unroll
        for (int p = 0; p < 8; p++) k2[p] = kp2[p];

        u64 ta0 = 0ull, ta1 = 0ull, ua0 = 0ull, ua1 = 0ull;
#pragma unroll
        for (int p = 0; p < 4; p++) {
            ta0 = ffma2(T2[p],     k2[p],     ta0);
            ta1 = ffma2(T2[p + 4], k2[p + 4], ta1);
            ua0 = ffma2(U2[p],     k2[p],     ua0);
            ua1 = ffma2(U2[p + 4], k2[p + 4], ua1);
        }
        float x0, x1, y0, y1, z0, z1, w0, w1;
        upk2(ta0, x0, x1); upk2(ta1, y0, y1);
        float Tk = (x0 + x1) + (y0 + y1);
        upk2(ua0, z0, z1); upk2(ua1, w0, w1);
        float Uk = (z0 + z1) + (w0 + w1);

        float a  = as_[tt * HEADS + h];
        float b  = bs [tt * HEADS + h];
        float vi = vs [tt * 64 + h * 16 + i];
        u64 cT2 = pk2(-a * Tk, -a * Tk);
        float cU = b * vi - a * Uk;
        u64 cU2 = pk2(cU, cU);

#pragma unroll
        for (int p = 0; p < 8; p++) {
            T2[p] = ffma2(k2[p], cT2, T2[p]);
            U2[p] = ffma2(k2[p], cU2, U2[p]);
        }
    }

    u64* Td = (u64*)(g_T + ((size_t)(n * NCHUNK + c) * HEADS + h) * 256 + i * 16);
    u64* Ud = (u64*)(g_U + ((size_t)(n * NCHUNK + c) * HEADS + h) * 256 + i * 16);
#pragma unroll
    for (int p = 0; p < 8; p++) { Td[p] = T2[p]; Ud[p] = U2[p]; }
}

// ---------------------------------------------------------------------------
// Scan pass 2 (packed): S_0 = 0 ; S_{c+1} = S_c T_c + U_c ; store S_c.
// ---------------------------------------------------------------------------
__global__ __launch_bounds__(64) void scan_phase2()
{
    const int n   = blockIdx.x;
    const int tid = threadIdx.x;
    const int h   = tid >> 4;
    const int i   = tid & 15;

    __shared__ __align__(16) float Ts[HEADS * 256];
    __shared__ __align__(16) float Us[HEADS * 256];

    float Sr[16];
#pragma unroll
    for (int j = 0; j < 16; j++) Sr[j] = 0.f;

    for (int c = 0; c < NCHUNK; c++) {
        const size_t ob = (size_t)(n * NCHUNK + c) * HEADS * 256;
        const float4* Tg = (const float4*)(g_T + ob);
        const float4* Ug = (const float4*)(g_U + ob);
#pragma unroll
        for (int idx = tid; idx < 256; idx += 64) {
            ((float4*)Ts)[idx] = Tg[idx];
            ((float4*)Us)[idx] = Ug[idx];
        }
        u64* Sd = (u64*)(g_S + ob + (size_t)h * 256 + i * 16);
#pragma unroll
        for (int p = 0; p < 8; p++) Sd[p] = pk2(Sr[2*p], Sr[2*p+1]);
        __syncthreads();

        u64 Sn2[8];
        const u64* Uh = (const u64*)(Us + h * 256 + i * 16);
#pragma unroll
        for (int p = 0; p < 8; p++) Sn2[p] = Uh[p];
        const float* Th = Ts + h * 256;
#pragma unroll
        for (int u = 0; u < 16; u++) {
            u64 su2 = pk2(Sr[u], Sr[u]);
            const u64* Tu = (const u64*)(Th + u * 16);
#pragma unroll
            for (int p = 0; p < 8; p++) Sn2[p] = ffma2(su2, Tu[p], Sn2[p]);
        }
#pragma unroll
        for (int p = 0; p < 8; p++) upk2(Sn2[p], Sr[2*p], Sr[2*p+1]);
        __syncthreads();
    }
}

// ---------------------------------------------------------------------------
// Scan pass 3 (packed): replay each chunk from its start state, emit outputs.
// ---------------------------------------------------------------------------
__global__ __launch_bounds__(64) void scan_phase3()
{
    const int n   = blockIdx.x;
    const int c   = blockIdx.y;
    const int tid = threadIdx.x;
    const int h   = tid >> 4;
    const int i   = tid & 15;

    __shared__ __align__(16) float ks[32 * 64];
    __shared__ __align__(16) float qs[32 * 64];
    __shared__ __align__(16) float vs[32 * 64];
    __shared__ float bs[32 * HEADS];
    __shared__ float as_[32 * HEADS];

    u64 M2[8];
    {
        const u64* Sg = (const u64*)(g_S +
            ((size_t)(n * NCHUNK + c) * HEADS + h) * 256 + i * 16);
#pragma unroll
        for (int p = 0; p < 8; p++) M2[p] = Sg[p];
    }

    for (int half = 0; half < 2; half++) {
        const size_t base  = ((size_t)n * TLEN + (size_t)c * CCH + half * 32) * 64;
        const size_t base2 = ((size_t)n * TLEN + (size_t)c * CCH + half * 32) * HEADS;
        {
            const float4* gk4 = (const float4*)(g_k + base);
            const float4* gq4 = (const float4*)(g_q + base);
            const float4* gv4 = (const float4*)(g_v + base);
#pragma unroll
            for (int idx = tid; idx < 32 * 16; idx += 64) {
                ((float4*)ks)[idx] = gk4[idx];
                ((float4*)qs)[idx] = gq4[idx];
                ((float4*)vs)[idx] = gv4[idx];
            }
#pragma unroll
            for (int idx = tid; idx < 32 * HEADS; idx += 64) {
                bs[idx]  = g_beta[base2 + idx];
                as_[idx] = g_alpha[base2 + idx];
            }
        }
        __syncthreads();

        for (int tt = 0; tt < 32; tt++) {
            const u64* kp2 = (const u64*)(ks + tt * 64 + h * 16);
            u64 k2[8];
#pragma unroll
            for (int p = 0; p < 8; p++) k2[p] = kp2[p];

            u64 s0 = 0ull, s1 = 0ull;
#pragma unroll
            for (int p = 0; p < 4; p++) {
                s0 = ffma2(M2[p],     k2[p],     s0);
                s1 = ffma2(M2[p + 4], k2[p + 4], s1);
            }
            float x0, x1, y0, y1;
            upk2(s0, x0, x1); upk2(s1, y0, y1);
            float Mk = (x0 + x1) + (y0 + y1);

            float a  = as_[tt * HEADS + h];
            float b  = bs [tt * HEADS + h];
            float vi = vs [tt * 64 + h * 16 + i];
            float cc = b * vi - a * Mk;
            u64 cc2 = pk2(cc, cc);

#pragma unroll
            for (int p = 0; p < 8; p++) M2[p] = ffma2(k2[p], cc2, M2[p]);

            const u64* qp2 = (const u64*)(qs + tt * 64 + h * 16);
            u64 o0 = 0ull, o1 = 0ull;
#pragma unroll
            for (int p = 0; p < 4; p++) {
                o0 = ffma2(M2[p],     qp2[p],     o0);
                o1 = ffma2(M2[p + 4], qp2[p + 4], o1);
            }
            float p0, p1, q0, q1;
            upk2(o0, p0, p1); upk2(o1, q0, q1);
            g_o[base + tt * 64 + h * 16 + i] = (p0 + p1) + (q0 + q1);
        }
        __syncthreads();
    }
}

// ---------------------------------------------------------------------------
// Kernel D (tf32 tensor): fib = o @ out_w^T + out_b, scatter to (B,T,P,K).
// ---------------------------------------------------------------------------
__global__ __launch_bounds__(128) void gemmD_kernel(const float* __restrict__ ob,
                                                    float* __restrict__ out)
{
    __shared__ __align__(16) float As[128][ASTR];
    __shared__ __align__(16) float Bs[32][BSTR];

    const int tid  = threadIdx.x;
    const int lane = tid & 31;
    const int wid  = tid >> 5;
    const int g    = lane >> 2;
    const int t    = lane & 3;
    const int wm   = (wid >> 1) * 64;
    const int wn   = (wid & 1) * 32;
    const int m0   = blockIdx.y * 128;
    const int n0   = blockIdx.x * 64;

    float acc[4][4][4];
#pragma unroll
    for (int i = 0; i < 4; i++)
#pragma unroll
        for (int j = 0; j < 4; j++)
#pragma unroll
            for (int r = 0; r < 4; r++) acc[i][j][r] = 0.f;

    for (int k0 = 0; k0 < 64; k0 += 32) {
#pragma unroll
        for (int i = 0; i < 8; i++) {
            int e   = i * 128 + tid;
            int row = e >> 3;
            int cq  = (e & 7) * 4;
            float4 av = *(const float4*)(g_o + (size_t)(m0 + row) * 64 + k0 + cq);
            float4 tv = make_float4(tf32r(av.x), tf32r(av.y), tf32r(av.z), tf32r(av.w));
            *(float4*)&As[row][cq] = tv;
        }
#pragma unroll
        for (int i = 0; i < 4; i++) {
            int e  = i * 128 + tid;
            int kk = e >> 4;
            int cq = (e & 15) * 4;
            float4 bv = *(const float4*)(g_Bpack2 + (size_t)(k0 + kk) * KOUT + n0 + cq);
            *(float4*)&Bs[kk][cq] = bv;
        }
        __syncthreads();

#pragma unroll
        for (int ks = 0; ks < 4; ks++) {
            const int kb = ks * 8;
            unsigned a[4][4], b[4][2];
#pragma unroll
            for (int mt = 0; mt < 4; mt++) {
                int r = wm + mt * 16 + g;
                a[mt][0] = fu(As[r][kb + t]);
                a[mt][1] = fu(As[r + 8][kb + t]);
                a[mt][2] = fu(As[r][kb + t + 4]);
                a[mt][3] = fu(As[r + 8][kb + t + 4]);
            }
#pragma unroll
            for (int nt = 0; nt < 4; nt++) {
                int n = wn + nt * 8 + g;
                b[nt][0] = fu(Bs[kb + t][n]);
                b[nt][1] = fu(Bs[kb + t + 4][n]);
            }
#pragma unroll
            for (int mt = 0; mt < 4; mt++)
#pragma unroll
                for (int nt = 0; nt < 4; nt++)
                    MMA_TF32(acc[mt][nt], a[mt], b[nt]);
        }
        __syncthreads();
    }

    const int nseq = m0 >> 11;
    const int tb   = m0 & 2047;
    const int bb   = nseq >> 4;
    const int pp   = nseq & 15;
#pragma unroll
    for (int mt = 0; mt < 4; mt++) {
#pragma unroll
        for (int nt = 0; nt < 4; nt++) {
            int r   = wm + mt * 16 + g;
            int col = n0 + wn + nt * 8 + 2 * t;
            float b0 = ob[col], b1 = ob[col + 1];
            int t1 = tb + r;
            size_t d1 = (((size_t)bb * TLEN + t1) * 16 + pp) * KOUT + col;
            *(float2*)(out + d1) = make_float2(acc[mt][nt][0] + b0,
                                               acc[mt][nt][1] + b1);
            int t2 = t1 + 8;
            size_t d2 = (((size_t)bb * TLEN + t2) * 16 + pp) * KOUT + col;
            *(float2*)(out + d2) = make_float2(acc[mt][nt][2] + b0,
                                               acc[mt][nt][3] + b1);
        }
    }
}

// ---------------------------------------------------------------------------
// launch
// ---------------------------------------------------------------------------
extern "C" void kernel_launch(void* const* d_in, const int* in_sizes, int n_in,
                              void* d_out, int out_size)
{
    const float* joint = (const float*)d_in[0];
    const float* curv  = (const float*)d_in[1];
    const float* ent   = (const float*)d_in[2];
    const float* Wq    = (const float*)d_in[3];
    const float* Wk    = (const float*)d_in[4];
    const float* Wv    = (const float*)d_in[5];
    const float* Wbw   = (const float*)d_in[6];
    const float* Wbb   = (const float*)d_in[7];
    const float* Waw   = (const float*)d_in[8];
    const float* Wab   = (const float*)d_in[9];
    const float* cw    = (const float*)d_in[10];
    const float* ew    = (const float*)d_in[11];
    const float* out_w = (const float*)d_in[12];
    const float* out_b = (const float*)d_in[13];
    const float* lqw   = (const float*)d_in[14];
    const float* lqb   = (const float*)d_in[15];
    const float* lkw   = (const float*)d_in[16];
    const float* lkb   = (const float*)d_in[17];
    float* out = (float*)d_out;

    pack_kernel<<<256, 256>>>(Wq, Wk, Wv, out_w);

    gemmA_kernel<<<dim3(3, M_TOK / 128), 128>>>(joint, lqw, lqb, lkw, lkb);

    beta_kernel<<<M_TOK / 8, 256>>>(joint, curv, ent, Wbw, Wbb, Waw, Wab, cw, ew);

    scan_phase1<<<dim3(NSEQ, NCHUNK), 64>>>();
    scan_phase2<<<NSEQ, 64>>>();
    scan_phase3<<<dim3(NSEQ, NCHUNK), 64>>>();

    gemmD_kernel<<<dim3(KOUT / 64, M_TOK / 128), 128>>>(out_b, out);
}

// round 10
// speedup vs baseline: 1.1300x; 1.1300x over previous
#include <cuda_runtime.h>
#include <cuda_bf16.h>
#include <math.h>

// ---------------------------------------------------------------------------
// B=4, T=2048, P=16, J=256, H=4, D=16, MEM=64, K_OUT=192
// N = B*P = 64 sequences; tokens M_TOK = 131072
// gemmA (tf32): q,k pre-acts -> g_pre (stride 128); v -> g_v direct.
// epilogue: LN(q), LN+L2(k), beta/alpha. Scan: chunked, 32-thr blocks,
// 2 rows/thread, f32x2 math. gemmD (tf32) + scatter.
// ---------------------------------------------------------------------------

#define M_TOK   131072
#define JDIM    256
#define NPRE    192
#define PSTR    128
#define NSEQ    64
#define TLEN    2048
#define HEADS   4
#define KOUT    192
#define CCH     64
#define NCHUNK  (TLEN / CCH)

typedef unsigned long long u64;

// -------- scratch (device globals; no allocation allowed) --------
__device__ float g_Bpack [(size_t)JDIM * NPRE];
__device__ float g_Bpack2[(size_t)64 * KOUT];
__device__ float g_pre   [(size_t)M_TOK * PSTR];
__device__ float g_q     [(size_t)M_TOK * 64];
__device__ float g_k     [(size_t)M_TOK * 64];
__device__ float g_v     [(size_t)M_TOK * 64];
__device__ float g_beta  [(size_t)M_TOK * HEADS];
__device__ float g_alpha [(size_t)M_TOK * HEADS];
__device__ float g_o     [(size_t)M_TOK * 64];
__device__ float g_T [(size_t)NSEQ * NCHUNK * HEADS * 256];
__device__ float g_U [(size_t)NSEQ * NCHUNK * HEADS * 256];
__device__ float g_S [(size_t)NSEQ * NCHUNK * HEADS * 256];

// ---- tf32 / packed-f32x2 helpers ----
__device__ __forceinline__ float tf32r(float x)
{
    unsigned u;
    asm("cvt.rna.tf32.f32 %0, %1;" : "=r"(u) : "f"(x));
    return __uint_as_float(u);
}
__device__ __forceinline__ unsigned fu(float x) { return __float_as_uint(x); }

__device__ __forceinline__ u64 pk2(float lo, float hi)
{
    u64 r;
    asm("mov.b64 %0, {%1, %2};" : "=l"(r) : "f"(lo), "f"(hi));
    return r;
}
__device__ __forceinline__ void upk2(u64 v, float& lo, float& hi)
{
    asm("mov.b64 {%0, %1}, %2;" : "=f"(lo), "=f"(hi) : "l"(v));
}
__device__ __forceinline__ u64 ffma2(u64 a, u64 b, u64 c)
{
    u64 d;
    asm("fma.rn.f32x2 %0, %1, %2, %3;" : "=l"(d) : "l"(a), "l"(b), "l"(c));
    return d;
}
// packed dot of 8-u64 row with 8-u64 k, two accumulator chains
__device__ __forceinline__ float pdot8(const u64* r, const u64* k)
{
    u64 a0 = 0ull, a1 = 0ull;
#pragma unroll
    for (int p = 0; p < 4; p++) {
        a0 = ffma2(r[p],     k[p],     a0);
        a1 = ffma2(r[p + 4], k[p + 4], a1);
    }
    float x0, x1, y0, y1;
    upk2(a0, x0, x1); upk2(a1, y0, y1);
    return (x0 + x1) + (y0 + y1);
}

#define MMA_TF32(c, a, b)                                                     \
    asm volatile("mma.sync.aligned.m16n8k8.row.col.f32.tf32.tf32.f32 "        \
                 "{%0,%1,%2,%3}, {%4,%5,%6,%7}, {%8,%9}, {%0,%1,%2,%3};"      \
                 : "+f"((c)[0]), "+f"((c)[1]), "+f"((c)[2]), "+f"((c)[3])     \
                 : "r"((a)[0]), "r"((a)[1]), "r"((a)[2]), "r"((a)[3]),        \
                   "r"((b)[0]), "r"((b)[1]))

// ---------------------------------------------------------------------------
// Kernel 0: pack weights (k-major) + round to tf32
// ---------------------------------------------------------------------------
__global__ void pack_kernel(const float* __restrict__ Wq,
                            const float* __restrict__ Wk,
                            const float* __restrict__ Wv,
                            const float* __restrict__ out_w)
{
    int idx = blockIdx.x * blockDim.x + threadIdx.x;
    if (idx < JDIM * NPRE) {
        int k = idx / NPRE;
        int o = idx - k * NPRE;
        float val;
        if      (o < 64)  val = Wq[(size_t)o       * JDIM + k];
        else if (o < 128) val = Wk[(size_t)(o-64)  * JDIM + k];
        else              val = Wv[(size_t)(o-128) * JDIM + k];
        g_Bpack[idx] = tf32r(val);
    }
    int idx2 = idx - JDIM * NPRE;
    if (idx2 >= 0 && idx2 < 64 * KOUT) {
        int k = idx2 / KOUT;
        int o = idx2 - k * KOUT;
        g_Bpack2[idx2] = tf32r(out_w[(size_t)o * 64 + k]);
    }
}

// ---------------------------------------------------------------------------
// warp reduction helpers
// ---------------------------------------------------------------------------
__device__ __forceinline__ float red16(float x)
{
    x += __shfl_xor_sync(0xffffffffu, x, 8);
    x += __shfl_xor_sync(0xffffffffu, x, 4);
    x += __shfl_xor_sync(0xffffffffu, x, 2);
    x += __shfl_xor_sync(0xffffffffu, x, 1);
    return x;
}
__device__ __forceinline__ float red32(float x)
{
    x += __shfl_xor_sync(0xffffffffu, x, 16);
    x += __shfl_xor_sync(0xffffffffu, x, 8);
    x += __shfl_xor_sync(0xffffffffu, x, 4);
    x += __shfl_xor_sync(0xffffffffu, x, 2);
    x += __shfl_xor_sync(0xffffffffu, x, 1);
    return x;
}
__device__ __forceinline__ float sigm(float x) { return 1.f / (1.f + expf(-x)); }

// ---------------------------------------------------------------------------
// Kernel A (tf32 tensor): bx=0 -> q pre (g_pre cols 0-63), bx=1 -> k pre
// (g_pre cols 64-127), bx=2 -> g_v direct. BM=128, BN=64, BK=32, 128 thr.
// ---------------------------------------------------------------------------
#define ASTR 36
#define BSTR 68

__global__ __launch_bounds__(128) void gemmA_kernel(const float* __restrict__ A)
{
    __shared__ __align__(16) float As[128][ASTR];
    __shared__ __align__(16) float Bs[32][BSTR];

    const int tid  = threadIdx.x;
    const int lane = tid & 31;
    const int wid  = tid >> 5;
    const int g    = lane >> 2;
    const int t    = lane & 3;
    const int wm   = (wid >> 1) * 64;
    const int wn   = (wid & 1) * 32;
    const int bx   = blockIdx.x;
    const int m0   = blockIdx.y * 128;
    const int n0   = bx * 64;

    float acc[4][4][4];
#pragma unroll
    for (int i = 0; i < 4; i++)
#pragma unroll
        for (int j = 0; j < 4; j++)
#pragma unroll
            for (int r = 0; r < 4; r++) acc[i][j][r] = 0.f;

    for (int k0 = 0; k0 < JDIM; k0 += 32) {
#pragma unroll
        for (int i = 0; i < 8; i++) {
            int e   = i * 128 + tid;
            int row = e >> 3;
            int cq  = (e & 7) * 4;
            float4 av = *(const float4*)(A + (size_t)(m0 + row) * JDIM + k0 + cq);
            float4 tv = make_float4(tf32r(av.x), tf32r(av.y), tf32r(av.z), tf32r(av.w));
            *(float4*)&As[row][cq] = tv;
        }
#pragma unroll
        for (int i = 0; i < 4; i++) {
            int e  = i * 128 + tid;
            int kk = e >> 4;
            int cq = (e & 15) * 4;
            float4 bv = *(const float4*)(g_Bpack + (size_t)(k0 + kk) * NPRE + n0 + cq);
            *(float4*)&Bs[kk][cq] = bv;
        }
        __syncthreads();

#pragma unroll
        for (int ks = 0; ks < 4; ks++) {
            const int kb = ks * 8;
            unsigned a[4][4], b[4][2];
#pragma unroll
            for (int mt = 0; mt < 4; mt++) {
                int r = wm + mt * 16 + g;
                a[mt][0] = fu(As[r][kb + t]);
                a[mt][1] = fu(As[r + 8][kb + t]);
                a[mt][2] = fu(As[r][kb + t + 4]);
                a[mt][3] = fu(As[r + 8][kb + t + 4]);
            }
#pragma unroll
            for (int nt = 0; nt < 4; nt++) {
                int n = wn + nt * 8 + g;
                b[nt][0] = fu(Bs[kb + t][n]);
                b[nt][1] = fu(Bs[kb + t + 4][n]);
            }
#pragma unroll
            for (int mt = 0; mt < 4; mt++)
#pragma unroll
                for (int nt = 0; nt < 4; nt++)
                    MMA_TF32(acc[mt][nt], a[mt], b[nt]);
        }
        __syncthreads();
    }

    float* dst   = (bx == 2) ? g_v : g_pre;
    int    cstr  = (bx == 2) ? 64  : PSTR;
    int    cbase = (bx == 2) ? 0   : bx * 64;
#pragma unroll
    for (int mt = 0; mt < 4; mt++) {
#pragma unroll
        for (int nt = 0; nt < 4; nt++) {
            int row = m0 + wm + mt * 16 + g;
            int col = cbase + wn + nt * 8 + 2 * t;
            *(float2*)(dst + (size_t)row * cstr + col) =
                make_float2(acc[mt][nt][0], acc[mt][nt][1]);
            *(float2*)(dst + (size_t)(row + 8) * cstr + col) =
                make_float2(acc[mt][nt][2], acc[mt][nt][3]);
        }
    }
}

// ---------------------------------------------------------------------------
// Kernel B: epilogue — LN(q), LN+L2(k) from g_pre; beta/alpha from x.
// One warp per token, 8 tokens/block.
// ---------------------------------------------------------------------------
__global__ __launch_bounds__(256) void epilogue_kernel(
    const float* __restrict__ x,
    const float* __restrict__ curv, const float* __restrict__ ent,
    const float* __restrict__ Wbw,  const float* __restrict__ Wbb,
    const float* __restrict__ Waw,  const float* __restrict__ Wab,
    const float* __restrict__ cw,   const float* __restrict__ ew,
    const float* __restrict__ lqw,  const float* __restrict__ lqb,
    const float* __restrict__ lkw,  const float* __restrict__ lkb)
{
    const int tid  = threadIdx.x;
    const int lane = tid & 31;
    const int w    = tid >> 5;
    const size_t m = (size_t)blockIdx.x * 8 + w;
    const float* pre = g_pre + m * PSTR;
    const int di = lane & 15;

    const float wq = lqw[di], bq = lqb[di];
    const float wk = lkw[di], bk = lkb[di];
    const float inv16 = 1.f / 16.f;

    float q0 = pre[lane], q1 = pre[32 + lane];
    float mu0 = red16(q0) * inv16, mu1 = red16(q1) * inv16;
    float d0 = q0 - mu0, d1 = q1 - mu1;
    float va0 = red16(d0 * d0) * inv16, va1 = red16(d1 * d1) * inv16;
    g_q[m * 64 + lane]      = d0 / sqrtf(va0 + 1e-5f) * wq + bq;
    g_q[m * 64 + 32 + lane] = d1 / sqrtf(va1 + 1e-5f) * wq + bq;

    float k0 = pre[64 + lane], k1 = pre[96 + lane];
    float km0 = red16(k0) * inv16, km1 = red16(k1) * inv16;
    float kd0 = k0 - km0, kd1 = k1 - km1;
    float kv0 = red16(kd0 * kd0) * inv16, kv1 = red16(kd1 * kd1) * inv16;
    float kn0 = kd0 / sqrtf(kv0 + 1e-5f) * wk + bk;
    float kn1 = kd1 / sqrtf(kv1 + 1e-5f) * wk + bk;
    float nn0 = red16(kn0 * kn0);
    float nn1 = red16(kn1 * kn1);
    g_k[m * 64 + lane]      = kn0 / fmaxf(sqrtf(nn0), 1e-12f);
    g_k[m * 64 + 32 + lane] = kn1 / fmaxf(sqrtf(nn1), 1e-12f);

    const float4* x4 = (const float4*)(x + m * JDIM);
    float4 xv0 = x4[lane * 2];
    float4 xv1 = x4[lane * 2 + 1];
    float par[8];
#pragma unroll
    for (int hh = 0; hh < 8; hh++) {
        const float* wr = (hh < 4) ? (Wbw + (size_t)hh * JDIM)
                                   : (Waw + (size_t)(hh - 4) * JDIM);
        float4 w0 = ((const float4*)wr)[lane * 2];
        float4 w1 = ((const float4*)wr)[lane * 2 + 1];
        float s = xv0.x * w0.x + xv0.y * w0.y + xv0.z * w0.z + xv0.w * w0.w
                + xv1.x * w1.x + xv1.y * w1.y + xv1.z * w1.z + xv1.w * w1.w;
        par[hh] = red32(s);
    }
    if (lane < HEADS) {
        int nidx = (int)(m >> 11);
        int bidx = nidx >> 4;
        float Kv = fminf(fabsf(curv[bidx]), 10.f);
        float Sv = fminf(fmaxf(ent[bidx], 0.f), 5.f);
        float b1 = sigm(par[lane] + Wbb[lane]);
        g_beta[m * HEADS + lane]  = sigm(b1 + Kv * cw[lane]);
        float a1 = sigm(par[4 + lane] + Wab[lane]);
        g_alpha[m * HEADS + lane] = sigm(a1 + Sv * ew[lane]);
    }
}

// ---------------------------------------------------------------------------
// Scan pass 1: 32-thread blocks, thread (h, i2) owns rows i2 and i2+8.
// Builds T = prod A_t and U = sum B_t prod A_s per (n, c, h).
// ---------------------------------------------------------------------------
__global__ __launch_bounds__(32) void scan_phase1()
{
    const int n   = blockIdx.x;
    const int c   = blockIdx.y;
    const int tid = threadIdx.x;
    const int h   = tid >> 3;
    const int i2  = tid & 7;
    const int r0  = i2;
    const int r1  = i2 + 8;

    __shared__ __align__(16) float ks[32 * 64];
    __shared__ __align__(16) float vs[32 * 64];
    __shared__ float bs[32 * HEADS];
    __shared__ float as_[32 * HEADS];

    u64 Ta[8], Tb[8], Ua[8], Ub[8];
#pragma unroll
    for (int p = 0; p < 8; p++) {
        Ta[p] = pk2((2*p == r0) ? 1.f : 0.f, (2*p+1 == r0) ? 1.f : 0.f);
        Tb[p] = pk2((2*p == r1) ? 1.f : 0.f, (2*p+1 == r1) ? 1.f : 0.f);
        Ua[p] = 0ull; Ub[p] = 0ull;
    }

    for (int half = 0; half < 2; half++) {
        const size_t base  = ((size_t)n * TLEN + (size_t)c * CCH + half * 32) * 64;
        const size_t base2 = ((size_t)n * TLEN + (size_t)c * CCH + half * 32) * HEADS;
        {
            const float4* gk4 = (const float4*)(g_k + base);
            const float4* gv4 = (const float4*)(g_v + base);
#pragma unroll
            for (int idx = tid; idx < 32 * 16; idx += 32) {
                ((float4*)ks)[idx] = gk4[idx];
                ((float4*)vs)[idx] = gv4[idx];
            }
#pragma unroll
            for (int idx = tid; idx < 32 * HEADS; idx += 32) {
                bs[idx]  = g_beta[base2 + idx];
                as_[idx] = g_alpha[base2 + idx];
            }
        }
        __syncthreads();

        for (int tt = 0; tt < 32; tt++) {
            const u64* kp2 = (const u64*)(ks + tt * 64 + h * 16);
            u64 k2[8];
#pragma unroll
            for (int p = 0; p < 8; p++) k2[p] = kp2[p];

            float Tka = pdot8(Ta, k2);
            float Tkb = pdot8(Tb, k2);
            float Uka = pdot8(Ua, k2);
            float Ukb = pdot8(Ub, k2);

            float a  = as_[tt * HEADS + h];
            float b  = bs [tt * HEADS + h];
            float va = vs [tt * 64 + h * 16 + r0];
            float vb = vs [tt * 64 + h * 16 + r1];
            float cTa = -a * Tka, cTb = -a * Tkb;
            float cUa = b * va - a * Uka;
            float cUb = b * vb - a * Ukb;
            u64 cTa2 = pk2(cTa, cTa), cTb2 = pk2(cTb, cTb);
            u64 cUa2 = pk2(cUa, cUa), cUb2 = pk2(cUb, cUb);

#pragma unroll
            for (int p = 0; p < 8; p++) {
                Ta[p] = ffma2(k2[p], cTa2, Ta[p]);
                Tb[p] = ffma2(k2[p], cTb2, Tb[p]);
                Ua[p] = ffma2(k2[p], cUa2, Ua[p]);
                Ub[p] = ffma2(k2[p], cUb2, Ub[p]);
            }
        }
        __syncthreads();
    }

    const size_t ob = ((size_t)(n * NCHUNK + c) * HEADS + h) * 256;
    u64* Td0 = (u64*)(g_T + ob + r0 * 16);
    u64* Td1 = (u64*)(g_T + ob + r1 * 16);
    u64* Ud0 = (u64*)(g_U + ob + r0 * 16);
    u64* Ud1 = (u64*)(g_U + ob + r1 * 16);
#pragma unroll
    for (int p = 0; p < 8; p++) {
        Td0[p] = Ta[p]; Td1[p] = Tb[p];
        Ud0[p] = Ua[p]; Ud1[p] = Ub[p];
    }
}

// ---------------------------------------------------------------------------
// Scan pass 2: compose chunk operators per (n,h) with LDG prefetch.
//   S_0 = 0 ; S_{c+1} = S_c T_c + U_c ; store S_c.
// ---------------------------------------------------------------------------
__global__ __launch_bounds__(64) void scan_phase2()
{
    const int n   = blockIdx.x;
    const int tid = threadIdx.x;
    const int h   = tid >> 4;
    const int i   = tid & 15;

    __shared__ __align__(16) float Ts[2][HEADS * 256];
    __shared__ __align__(16) float Us[2][HEADS * 256];

    float Sr[16];
#pragma unroll
    for (int j = 0; j < 16; j++) Sr[j] = 0.f;

    // preload chunk 0
    {
        const size_t ob = (size_t)(n * NCHUNK) * HEADS * 256;
        const float4* Tg = (const float4*)(g_T + ob);
        const float4* Ug = (const float4*)(g_U + ob);
#pragma unroll
        for (int j = 0; j < 4; j++) {
            ((float4*)Ts[0])[tid + j * 64] = Tg[tid + j * 64];
            ((float4*)Us[0])[tid + j * 64] = Ug[tid + j * 64];
        }
    }
    __syncthreads();

    for (int c = 0; c < NCHUNK; c++) {
        const int cur = c & 1;
        // prefetch next chunk into registers (LDG issued before compute)
        float4 pfT[4], pfU[4];
        if (c + 1 < NCHUNK) {
            const size_t obn = (size_t)(n * NCHUNK + c + 1) * HEADS * 256;
            const float4* Tg = (const float4*)(g_T + obn);
            const float4* Ug = (const float4*)(g_U + obn);
#pragma unroll
            for (int j = 0; j < 4; j++) {
                pfT[j] = Tg[tid + j * 64];
                pfU[j] = Ug[tid + j * 64];
            }
        }

        // store S_c (state at start of chunk c)
        {
            const size_t ob = (size_t)(n * NCHUNK + c) * HEADS * 256;
            float* Sd = g_S + ob + (size_t)h * 256 + i * 16;
#pragma unroll
            for (int j = 0; j < 4; j++)
                *(float4*)(Sd + 4*j) = make_float4(Sr[4*j], Sr[4*j+1],
                                                   Sr[4*j+2], Sr[4*j+3]);
        }

        // S = S*T + U
        u64 Sn2[8];
        const u64* Uh = (const u64*)(Us[cur] + h * 256 + i * 16);
#pragma unroll
        for (int p = 0; p < 8; p++) Sn2[p] = Uh[p];
        const float* Th = Ts[cur] + h * 256;
#pragma unroll
        for (int u = 0; u < 16; u++) {
            u64 su2 = pk2(Sr[u], Sr[u]);
            const u64* Tu = (const u64*)(Th + u * 16);
#pragma unroll
            for (int p = 0; p < 8; p++) Sn2[p] = ffma2(su2, Tu[p], Sn2[p]);
        }
#pragma unroll
        for (int p = 0; p < 8; p++) upk2(Sn2[p], Sr[2*p], Sr[2*p+1]);

        // commit prefetch to the other buffer
        if (c + 1 < NCHUNK) {
#pragma unroll
            for (int j = 0; j < 4; j++) {
                ((float4*)Ts[cur ^ 1])[tid + j * 64] = pfT[j];
                ((float4*)Us[cur ^ 1])[tid + j * 64] = pfU[j];
            }
        }
        __syncthreads();
    }
}

// ---------------------------------------------------------------------------
// Scan pass 3: 32-thread blocks, 2 rows/thread. Replay chunk from S_c,
// emit o_t = M_t q_t. Staged in 16-step quarters.
// ---------------------------------------------------------------------------
__global__ __launch_bounds__(32) void scan_phase3()
{
    const int n   = blockIdx.x;
    const int c   = blockIdx.y;
    const int tid = threadIdx.x;
    const int h   = tid >> 3;
    const int i2  = tid & 7;
    const int r0  = i2;
    const int r1  = i2 + 8;

    __shared__ __align__(16) float ks[16 * 64];
    __shared__ __align__(16) float qs[16 * 64];
    __shared__ __align__(16) float vs[16 * 64];
    __shared__ float bs[16 * HEADS];
    __shared__ float as_[16 * HEADS];

    u64 Ma[8], Mb[8];
    {
        const size_t ob = ((size_t)(n * NCHUNK + c) * HEADS + h) * 256;
        const u64* S0 = (const u64*)(g_S + ob + r0 * 16);
        const u64* S1 = (const u64*)(g_S + ob + r1 * 16);
#pragma unroll
        for (int p = 0; p < 8; p++) { Ma[p] = S0[p]; Mb[p] = S1[p]; }
    }

    for (int qt = 0; qt < 4; qt++) {
        const size_t base  = ((size_t)n * TLEN + (size_t)c * CCH + qt * 16) * 64;
        const size_t base2 = ((size_t)n * TLEN + (size_t)c * CCH + qt * 16) * HEADS;
        {
            const float4* gk4 = (const float4*)(g_k + base);
            const float4* gq4 = (const float4*)(g_q + base);
            const float4* gv4 = (const float4*)(g_v + base);
#pragma unroll
            for (int idx = tid; idx < 16 * 16; idx += 32) {
                ((float4*)ks)[idx] = gk4[idx];
                ((float4*)qs)[idx] = gq4[idx];
                ((float4*)vs)[idx] = gv4[idx];
            }
#pragma unroll
            for (int idx = tid; idx < 16 * HEADS; idx += 32) {
                bs[idx]  = g_beta[base2 + idx];
                as_[idx] = g_alpha[base2 + idx];
            }
        }
        __syncthreads();

        for (int tt = 0; tt < 16; tt++) {
            const u64* kp2 = (const u64*)(ks + tt * 64 + h * 16);
            u64 k2[8];
#pragma unroll
            for (int p = 0; p < 8; p++) k2[p] = kp2[p];

            float Mka = pdot8(Ma, k2);
            float Mkb = pdot8(Mb, k2);

            float a  = as_[tt * HEADS + h];
            float b  = bs [tt * HEADS + h];
            float va = vs [tt * 64 + h * 16 + r0];
            float vb = vs [tt * 64 + h * 16 + r1];
            float ca = b * va - a * Mka;
            float cb = b * vb - a * Mkb;
            u64 ca2 = pk2(ca, ca), cb2 = pk2(cb, cb);

#pragma unroll
            for (int p = 0; p < 8; p++) {
                Ma[p] = ffma2(k2[p], ca2, Ma[p]);
                Mb[p] = ffma2(k2[p], cb2, Mb[p]);
            }

            const u64* qp2 = (const u64*)(qs + tt * 64 + h * 16);
            u64 q2[8];
#pragma unroll
            for (int p = 0; p < 8; p++) q2[p] = qp2[p];
            float oa = pdot8(Ma, q2);
            float ob_ = pdot8(Mb, q2);

            g_o[base + tt * 64 + h * 16 + r0] = oa;
            g_o[base + tt * 64 + h * 16 + r1] = ob_;
        }
        __syncthreads();
    }
}

// ---------------------------------------------------------------------------
// Kernel D (tf32 tensor): fib = o @ out_w^T + out_b, scatter to (B,T,P,K).
// ---------------------------------------------------------------------------
__global__ __launch_bounds__(128) void gemmD_kernel(const float* __restrict__ ob,
                                                    float* __restrict__ out)
{
    __shared__ __align__(16) float As[128][ASTR];
    __shared__ __align__(16) float Bs[32][BSTR];

    const int tid  = threadIdx.x;
    const int lane = tid & 31;
    const int wid  = tid >> 5;
    const int g    = lane >> 2;
    const int t    = lane & 3;
    const int wm   = (wid >> 1) * 64;
    const int wn   = (wid & 1) * 32;
    const int m0   = blockIdx.y * 128;
    const int n0   = blockIdx.x * 64;

    float acc[4][4][4];
#pragma unroll
    for (int i = 0; i < 4; i++)
#pragma unroll
        for (int j = 0; j < 4; j++)
#pragma unroll
            for (int r = 0; r < 4; r++) acc[i][j][r] = 0.f;

    for (int k0 = 0; k0 < 64; k0 += 32) {
#pragma unroll
        for (int i = 0; i < 8; i++) {
            int e   = i * 128 + tid;
            int row = e >> 3;
            int cq  = (e & 7) * 4;
            float4 av = *(const float4*)(g_o + (size_t)(m0 + row) * 64 + k0 + cq);
            float4 tv = make_float4(tf32r(av.x), tf32r(av.y), tf32r(av.z), tf32r(av.w));
            *(float4*)&As[row][cq] = tv;
        }
#pragma unroll
        for (int i = 0; i < 4; i++) {
            int e  = i * 128 + tid;
            int kk = e >> 4;
            int cq = (e & 15) * 4;
            float4 bv = *(const float4*)(g_Bpack2 + (size_t)(k0 + kk) * KOUT + n0 + cq);
            *(float4*)&Bs[kk][cq] = bv;
        }
        __syncthreads();

#pragma unroll
        for (int ks = 0; ks < 4; ks++) {
            const int kb = ks * 8;
            unsigned a[4][4], b[4][2];
#pragma unroll
            for (int mt = 0; mt < 4; mt++) {
                int r = wm + mt * 16 + g;
                a[mt][0] = fu(As[r][kb + t]);
                a[mt][1] = fu(As[r + 8][kb + t]);
                a[mt][2] = fu(As[r][kb + t + 4]);
                a[mt][3] = fu(As[r + 8][kb + t + 4]);
            }
#pragma unroll
            for (int nt = 0; nt < 4; nt++) {
                int n = wn + nt * 8 + g;
                b[nt][0] = fu(Bs[kb + t][n]);
                b[nt][1] = fu(Bs[kb + t + 4][n]);
            }
#pragma unroll
            for (int mt = 0; mt < 4; mt++)
#pragma unroll
                for (int nt = 0; nt < 4; nt++)
                    MMA_TF32(acc[mt][nt], a[mt], b[nt]);
        }
        __syncthreads();
    }

    const int nseq = m0 >> 11;
    const int tb   = m0 & 2047;
    const int bb   = nseq >> 4;
    const int pp   = nseq & 15;
#pragma unroll
    for (int mt = 0; mt < 4; mt++) {
#pragma unroll
        for (int nt = 0; nt < 4; nt++) {
            int r   = wm + mt * 16 + g;
            int col = n0 + wn + nt * 8 + 2 * t;
            float b0 = ob[col], b1 = ob[col + 1];
            int t1 = tb + r;
            size_t d1 = (((size_t)bb * TLEN + t1) * 16 + pp) * KOUT + col;
            *(float2*)(out + d1) = make_float2(acc[mt][nt][0] + b0,
                                               acc[mt][nt][1] + b1);
            int t2 = t1 + 8;
            size_t d2 = (((size_t)bb * TLEN + t2) * 16 + pp) * KOUT + col;
            *(float2*)(out + d2) = make_float2(acc[mt][nt][2] + b0,
                                               acc[mt][nt][3] + b1);
        }
    }
}

// ---------------------------------------------------------------------------
// launch
// ---------------------------------------------------------------------------
extern "C" void kernel_launch(void* const* d_in, const int* in_sizes, int n_in,
                              void* d_out, int out_size)
{
    const float* joint = (const float*)d_in[0];
    const float* curv  = (const float*)d_in[1];
    const float* ent   = (const float*)d_in[2];
    const float* Wq    = (const float*)d_in[3];
    const float* Wk    = (const float*)d_in[4];
    const float* Wv    = (const float*)d_in[5];
    const float* Wbw   = (const float*)d_in[6];
    const float* Wbb   = (const float*)d_in[7];
    const float* Waw   = (const float*)d_in[8];
    const float* Wab   = (const float*)d_in[9];
    const float* cw    = (const float*)d_in[10];
    const float* ew    = (const float*)d_in[11];
    const float* out_w = (const float*)d_in[12];
    const float* out_b = (const float*)d_in[13];
    const float* lqw   = (const float*)d_in[14];
    const float* lqb   = (const float*)d_in[15];
    const float* lkw   = (const float*)d_in[16];
    const float* lkb   = (const float*)d_in[17];
    float* out = (float*)d_out;

    pack_kernel<<<256, 256>>>(Wq, Wk, Wv, out_w);

    gemmA_kernel<<<dim3(3, M_TOK / 128), 128>>>(joint);

    epilogue_kernel<<<M_TOK / 8, 256>>>(joint, curv, ent, Wbw, Wbb, Waw, Wab,
                                        cw, ew, lqw, lqb, lkw, lkb);

    scan_phase1<<<dim3(NSEQ, NCHUNK), 32>>>();
    scan_phase2<<<NSEQ, 64>>>();
    scan_phase3<<<dim3(NSEQ, NCHUNK), 32>>>();

    gemmD_kernel<<<dim3(KOUT / 64, M_TOK / 128), 128>>>(out_b, out);
}

// round 11
// speedup vs baseline: 1.2393x; 1.0967x over previous
#include <cuda_runtime.h>
#include <cuda_bf16.h>
#include <math.h>

// ---------------------------------------------------------------------------
// B=4, T=2048, P=16, J=256, H=4, D=16, MEM=64, K_OUT=192
// N = B*P = 64 sequences; tokens M_TOK = 131072
// gemmA (tf32, cp.async 2-stage): q -> LN -> g_q, k -> LN+L2 -> g_k (fused
// in-register via quad shuffles), v -> g_v. beta/alpha kernel. Chunked scan.
// gemmD (tf32) + scatter.
// ---------------------------------------------------------------------------

#define M_TOK   131072
#define JDIM    256
#define NPRE    192
#define NSEQ    64
#define TLEN    2048
#define HEADS   4
#define KOUT    192
#define CCH     64
#define NCHUNK  (TLEN / CCH)

typedef unsigned long long u64;

// -------- scratch (device globals; no allocation allowed) --------
__device__ float g_Bpack [(size_t)JDIM * NPRE];
__device__ float g_Bpack2[(size_t)64 * KOUT];
__device__ float g_q     [(size_t)M_TOK * 64];
__device__ float g_k     [(size_t)M_TOK * 64];
__device__ float g_v     [(size_t)M_TOK * 64];
__device__ float g_beta  [(size_t)M_TOK * HEADS];
__device__ float g_alpha [(size_t)M_TOK * HEADS];
__device__ float g_o     [(size_t)M_TOK * 64];
__device__ float g_T [(size_t)NSEQ * NCHUNK * HEADS * 256];
__device__ float g_U [(size_t)NSEQ * NCHUNK * HEADS * 256];
__device__ float g_S [(size_t)NSEQ * NCHUNK * HEADS * 256];

// ---- helpers ----
__device__ __forceinline__ float tf32r(float x)
{
    unsigned u;
    asm("cvt.rna.tf32.f32 %0, %1;" : "=r"(u) : "f"(x));
    return __uint_as_float(u);
}
__device__ __forceinline__ unsigned fu(float x) { return __float_as_uint(x); }
__device__ __forceinline__ unsigned futf(float x)
{
    unsigned u;
    asm("cvt.rna.tf32.f32 %0, %1;" : "=r"(u) : "f"(x));
    return u;
}

__device__ __forceinline__ u64 pk2(float lo, float hi)
{
    u64 r;
    asm("mov.b64 %0, {%1, %2};" : "=l"(r) : "f"(lo), "f"(hi));
    return r;
}
__device__ __forceinline__ void upk2(u64 v, float& lo, float& hi)
{
    asm("mov.b64 {%0, %1}, %2;" : "=f"(lo), "=f"(hi) : "l"(v));
}
__device__ __forceinline__ u64 ffma2(u64 a, u64 b, u64 c)
{
    u64 d;
    asm("fma.rn.f32x2 %0, %1, %2, %3;" : "=l"(d) : "l"(a), "l"(b), "l"(c));
    return d;
}
__device__ __forceinline__ float pdot8(const u64* r, const u64* k)
{
    u64 a0 = 0ull, a1 = 0ull;
#pragma unroll
    for (int p = 0; p < 4; p++) {
        a0 = ffma2(r[p],     k[p],     a0);
        a1 = ffma2(r[p + 4], k[p + 4], a1);
    }
    float x0, x1, y0, y1;
    upk2(a0, x0, x1); upk2(a1, y0, y1);
    return (x0 + x1) + (y0 + y1);
}

__device__ __forceinline__ unsigned su32(const void* p)
{
    return (unsigned)__cvta_generic_to_shared(p);
}
#define CP16(dst, src) \
    asm volatile("cp.async.cg.shared.global [%0], [%1], 16;" :: "r"(dst), "l"(src))
#define CP_COMMIT() asm volatile("cp.async.commit_group;")
#define CP_WAIT1()  asm volatile("cp.async.wait_group 1;")
#define CP_WAIT0()  asm volatile("cp.async.wait_group 0;")

#define MMA_TF32(c, a, b)                                                     \
    asm volatile("mma.sync.aligned.m16n8k8.row.col.f32.tf32.tf32.f32 "        \
                 "{%0,%1,%2,%3}, {%4,%5,%6,%7}, {%8,%9}, {%0,%1,%2,%3};"      \
                 : "+f"((c)[0]), "+f"((c)[1]), "+f"((c)[2]), "+f"((c)[3])     \
                 : "r"((a)[0]), "r"((a)[1]), "r"((a)[2]), "r"((a)[3]),        \
                   "r"((b)[0]), "r"((b)[1]))

// quad butterfly (over t = lane&3)
__device__ __forceinline__ float qred(float x)
{
    x += __shfl_xor_sync(0xffffffffu, x, 1);
    x += __shfl_xor_sync(0xffffffffu, x, 2);
    return x;
}
__device__ __forceinline__ float red32(float x)
{
    x += __shfl_xor_sync(0xffffffffu, x, 16);
    x += __shfl_xor_sync(0xffffffffu, x, 8);
    x += __shfl_xor_sync(0xffffffffu, x, 4);
    x += __shfl_xor_sync(0xffffffffu, x, 2);
    x += __shfl_xor_sync(0xffffffffu, x, 1);
    return x;
}
__device__ __forceinline__ float sigm(float x) { return 1.f / (1.f + expf(-x)); }

// ---------------------------------------------------------------------------
// Kernel 0: pack weights (k-major) + round to tf32
// ---------------------------------------------------------------------------
__global__ void pack_kernel(const float* __restrict__ Wq,
                            const float* __restrict__ Wk,
                            const float* __restrict__ Wv,
                            const float* __restrict__ out_w)
{
    int idx = blockIdx.x * blockDim.x + threadIdx.x;
    if (idx < JDIM * NPRE) {
        int k = idx / NPRE;
        int o = idx - k * NPRE;
        float val;
        if      (o < 64)  val = Wq[(size_t)o       * JDIM + k];
        else if (o < 128) val = Wk[(size_t)(o-64)  * JDIM + k];
        else              val = Wv[(size_t)(o-128) * JDIM + k];
        g_Bpack[idx] = tf32r(val);
    }
    int idx2 = idx - JDIM * NPRE;
    if (idx2 >= 0 && idx2 < 64 * KOUT) {
        int k = idx2 / KOUT;
        int o = idx2 - k * KOUT;
        g_Bpack2[idx2] = tf32r(out_w[(size_t)o * 64 + k]);
    }
}

// ---------------------------------------------------------------------------
// Kernel A: tf32 GEMM, BM=128 BN=64 BK=16, cp.async 2-stage, 128 threads.
// bx=0: q -> fused LN -> g_q ; bx=1: k -> fused LN + L2 -> g_k ; bx=2: v.
// ---------------------------------------------------------------------------
#define A_KS  20   // A smem stride (conflict-free: 20g mod 32 distinct)
#define B_KS  68

__global__ __launch_bounds__(128) void gemmA_kernel(
    const float* __restrict__ A,
    const float* __restrict__ lqw, const float* __restrict__ lqb,
    const float* __restrict__ lkw, const float* __restrict__ lkb)
{
    __shared__ __align__(16) float As[2][128][A_KS];
    __shared__ __align__(16) float Bs[2][16][B_KS];

    const int tid  = threadIdx.x;
    const int lane = tid & 31;
    const int wid  = tid >> 5;
    const int g    = lane >> 2;
    const int t    = lane & 3;
    const int wm   = (wid >> 1) * 64;
    const int wn   = (wid & 1) * 32;
    const int bx   = blockIdx.x;
    const int m0   = blockIdx.y * 128;
    const int n0   = bx * 64;

    // load-tile addresses (A: 4 float4/thread, B: 2 float4/thread)
    const int arow = tid >> 2;          // wrong for 4/thread pattern; compute in loop
    (void)arow;

    float acc[4][4][4];
#pragma unroll
    for (int i = 0; i < 4; i++)
#pragma unroll
        for (int j = 0; j < 4; j++)
#pragma unroll
            for (int r = 0; r < 4; r++) acc[i][j][r] = 0.f;

    auto load_tiles = [&](int k0, int buf) {
#pragma unroll
        for (int i = 0; i < 4; i++) {
            int e   = i * 128 + tid;
            int row = e >> 2;           // 4 float4 per row (16 cols)
            int cq  = (e & 3) * 4;
            CP16(su32(&As[buf][row][cq]),
                 A + (size_t)(m0 + row) * JDIM + k0 + cq);
        }
#pragma unroll
        for (int i = 0; i < 2; i++) {
            int e  = i * 128 + tid;
            int kk = e >> 4;            // 16 float4 per row (64 cols)
            int cq = (e & 15) * 4;
            CP16(su32(&Bs[buf][kk][cq]),
                 g_Bpack + (size_t)(k0 + kk) * NPRE + n0 + cq);
        }
    };

    load_tiles(0, 0);
    CP_COMMIT();

    for (int kt = 0; kt < 16; kt++) {
        const int cur = kt & 1;
        if (kt < 15) {
            load_tiles((kt + 1) * 16, cur ^ 1);
            CP_COMMIT();
            CP_WAIT1();
        } else {
            CP_WAIT0();
        }
        __syncthreads();

#pragma unroll
        for (int ks = 0; ks < 2; ks++) {
            const int kb = ks * 8;
            unsigned a[4][4], b[4][2];
#pragma unroll
            for (int mt = 0; mt < 4; mt++) {
                int r = wm + mt * 16 + g;
                a[mt][0] = futf(As[cur][r][kb + t]);
                a[mt][1] = futf(As[cur][r + 8][kb + t]);
                a[mt][2] = futf(As[cur][r][kb + t + 4]);
                a[mt][3] = futf(As[cur][r + 8][kb + t + 4]);
            }
#pragma unroll
            for (int nt = 0; nt < 4; nt++) {
                int n = wn + nt * 8 + g;
                b[nt][0] = fu(Bs[cur][kb + t][n]);
                b[nt][1] = fu(Bs[cur][kb + t + 4][n]);
            }
#pragma unroll
            for (int mt = 0; mt < 4; mt++)
#pragma unroll
                for (int nt = 0; nt < 4; nt++)
                    MMA_TF32(acc[mt][nt], a[mt], b[nt]);
        }
        __syncthreads();
    }

    if (bx == 2) {
        // v: direct store
#pragma unroll
        for (int mt = 0; mt < 4; mt++) {
#pragma unroll
            for (int nt = 0; nt < 4; nt++) {
                int row = m0 + wm + mt * 16 + g;
                int col = wn + nt * 8 + 2 * t;
                *(float2*)(g_v + (size_t)row * 64 + col) =
                    make_float2(acc[mt][nt][0], acc[mt][nt][1]);
                *(float2*)(g_v + (size_t)(row + 8) * 64 + col) =
                    make_float2(acc[mt][nt][2], acc[mt][nt][3]);
            }
        }
        return;
    }

    // q/k: fused LayerNorm (+L2 for k) in registers via quad butterflies.
    // Head hl (0/1) of this warp's 32-col slab: values live in nt=2hl,2hl+1;
    // each thread holds 4 of 16 row-values at ln-indices {2t,2t+1,8+2t,8+2t+1}.
    const float* wp = (bx == 0) ? lqw : lkw;
    const float* bp = (bx == 0) ? lqb : lkb;
    float wv0 = wp[2 * t], wv1 = wp[2 * t + 1];
    float wv2 = wp[8 + 2 * t], wv3 = wp[8 + 2 * t + 1];
    float bb0 = bp[2 * t], bb1 = bp[2 * t + 1];
    float bb2 = bp[8 + 2 * t], bb3 = bp[8 + 2 * t + 1];
    float* dst = (bx == 0) ? g_q : g_k;
    const float inv16 = 1.f / 16.f;

#pragma unroll
    for (int mt = 0; mt < 4; mt++) {
#pragma unroll
        for (int hl = 0; hl < 2; hl++) {
            const int nt0 = 2 * hl, nt1 = 2 * hl + 1;
#pragma unroll
            for (int half = 0; half < 2; half++) {
                const int c0 = half * 2, c1 = half * 2 + 1;
                float x0 = acc[mt][nt0][c0], x1 = acc[mt][nt0][c1];
                float x2 = acc[mt][nt1][c0], x3 = acc[mt][nt1][c1];
                float mu = qred(x0 + x1 + x2 + x3) * inv16;
                float d0 = x0 - mu, d1 = x1 - mu, d2 = x2 - mu, d3 = x3 - mu;
                float var = qred(d0*d0 + d1*d1 + d2*d2 + d3*d3) * inv16;
                float rs = 1.f / sqrtf(var + 1e-5f);
                float n0v = d0 * rs * wv0 + bb0;
                float n1v = d1 * rs * wv1 + bb1;
                float n2v = d2 * rs * wv2 + bb2;
                float n3v = d3 * rs * wv3 + bb3;
                if (bx == 1) {
                    float ss = qred(n0v*n0v + n1v*n1v + n2v*n2v + n3v*n3v);
                    float sc = 1.f / fmaxf(sqrtf(ss), 1e-12f);
                    n0v *= sc; n1v *= sc; n2v *= sc; n3v *= sc;
                }
                int row = m0 + wm + mt * 16 + g + half * 8;
                int cb  = wn + hl * 16 + 2 * t;
                *(float2*)(dst + (size_t)row * 64 + cb)     = make_float2(n0v, n1v);
                *(float2*)(dst + (size_t)row * 64 + cb + 8) = make_float2(n2v, n3v);
            }
        }
    }
}

// ---------------------------------------------------------------------------
// Kernel B: beta/alpha only (warp per token)
// ---------------------------------------------------------------------------
__global__ __launch_bounds__(256) void beta_kernel(
    const float* __restrict__ x,
    const float* __restrict__ curv, const float* __restrict__ ent,
    const float* __restrict__ Wbw,  const float* __restrict__ Wbb,
    const float* __restrict__ Waw,  const float* __restrict__ Wab,
    const float* __restrict__ cw,   const float* __restrict__ ew)
{
    const int tid  = threadIdx.x;
    const int lane = tid & 31;
    const int w    = tid >> 5;
    const size_t m = (size_t)blockIdx.x * 8 + w;

    const float4* x4 = (const float4*)(x + m * JDIM);
    float4 xv0 = x4[lane * 2];
    float4 xv1 = x4[lane * 2 + 1];
    float par[8];
#pragma unroll
    for (int hh = 0; hh < 8; hh++) {
        const float* wr = (hh < 4) ? (Wbw + (size_t)hh * JDIM)
                                   : (Waw + (size_t)(hh - 4) * JDIM);
        float4 w0 = ((const float4*)wr)[lane * 2];
        float4 w1 = ((const float4*)wr)[lane * 2 + 1];
        float s = xv0.x * w0.x + xv0.y * w0.y + xv0.z * w0.z + xv0.w * w0.w
                + xv1.x * w1.x + xv1.y * w1.y + xv1.z * w1.z + xv1.w * w1.w;
        par[hh] = red32(s);
    }
    if (lane < HEADS) {
        int nidx = (int)(m >> 11);
        int bidx = nidx >> 4;
        float Kv = fminf(fabsf(curv[bidx]), 10.f);
        float Sv = fminf(fmaxf(ent[bidx], 0.f), 5.f);
        float b1 = sigm(par[lane] + Wbb[lane]);
        g_beta[m * HEADS + lane]  = sigm(b1 + Kv * cw[lane]);
        float a1 = sigm(par[4 + lane] + Wab[lane]);
        g_alpha[m * HEADS + lane] = sigm(a1 + Sv * ew[lane]);
    }
}

// ---------------------------------------------------------------------------
// Scan pass 1: 32-thread blocks, thread (h, i2) owns rows i2 and i2+8.
// ---------------------------------------------------------------------------
__global__ __launch_bounds__(32) void scan_phase1()
{
    const int n   = blockIdx.x;
    const int c   = blockIdx.y;
    const int tid = threadIdx.x;
    const int h   = tid >> 3;
    const int i2  = tid & 7;
    const int r0  = i2;
    const int r1  = i2 + 8;

    __shared__ __align__(16) float ks[32 * 64];
    __shared__ __align__(16) float vs[32 * 64];
    __shared__ float bs[32 * HEADS];
    __shared__ float as_[32 * HEADS];

    u64 Ta[8], Tb[8], Ua[8], Ub[8];
#pragma unroll
    for (int p = 0; p < 8; p++) {
        Ta[p] = pk2((2*p == r0) ? 1.f : 0.f, (2*p+1 == r0) ? 1.f : 0.f);
        Tb[p] = pk2((2*p == r1) ? 1.f : 0.f, (2*p+1 == r1) ? 1.f : 0.f);
        Ua[p] = 0ull; Ub[p] = 0ull;
    }

    for (int half = 0; half < 2; half++) {
        const size_t base  = ((size_t)n * TLEN + (size_t)c * CCH + half * 32) * 64;
        const size_t base2 = ((size_t)n * TLEN + (size_t)c * CCH + half * 32) * HEADS;
        {
            const float4* gk4 = (const float4*)(g_k + base);
            const float4* gv4 = (const float4*)(g_v + base);
#pragma unroll
            for (int idx = tid; idx < 32 * 16; idx += 32) {
                ((float4*)ks)[idx] = gk4[idx];
                ((float4*)vs)[idx] = gv4[idx];
            }
#pragma unroll
            for (int idx = tid; idx < 32 * HEADS; idx += 32) {
                bs[idx]  = g_beta[base2 + idx];
                as_[idx] = g_alpha[base2 + idx];
            }
        }
        __syncthreads();

        for (int tt = 0; tt < 32; tt++) {
            const u64* kp2 = (const u64*)(ks + tt * 64 + h * 16);
            u64 k2[8];
#pragma unroll
            for (int p = 0; p < 8; p++) k2[p] = kp2[p];

            float Tka = pdot8(Ta, k2);
            float Tkb = pdot8(Tb, k2);
            float Uka = pdot8(Ua, k2);
            float Ukb = pdot8(Ub, k2);

            float a  = as_[tt * HEADS + h];
            float b  = bs [tt * HEADS + h];
            float va = vs [tt * 64 + h * 16 + r0];
            float vb = vs [tt * 64 + h * 16 + r1];
            float cTa = -a * Tka, cTb = -a * Tkb;
            float cUa = b * va - a * Uka;
            float cUb = b * vb - a * Ukb;
            u64 cTa2 = pk2(cTa, cTa), cTb2 = pk2(cTb, cTb);
            u64 cUa2 = pk2(cUa, cUa), cUb2 = pk2(cUb, cUb);

#pragma unroll
            for (int p = 0; p < 8; p++) {
                Ta[p] = ffma2(k2[p], cTa2, Ta[p]);
                Tb[p] = ffma2(k2[p], cTb2, Tb[p]);
                Ua[p] = ffma2(k2[p], cUa2, Ua[p]);
                Ub[p] = ffma2(k2[p], cUb2, Ub[p]);
            }
        }
        __syncthreads();
    }

    const size_t ob = ((size_t)(n * NCHUNK + c) * HEADS + h) * 256;
    u64* Td0 = (u64*)(g_T + ob + r0 * 16);
    u64* Td1 = (u64*)(g_T + ob + r1 * 16);
    u64* Ud0 = (u64*)(g_U + ob + r0 * 16);
    u64* Ud1 = (u64*)(g_U + ob + r1 * 16);
#pragma unroll
    for (int p = 0; p < 8; p++) {
        Td0[p] = Ta[p]; Td1[p] = Tb[p];
        Ud0[p] = Ua[p]; Ud1[p] = Ub[p];
    }
}

// ---------------------------------------------------------------------------
// Scan pass 2: compose chunk operators per (n,h) with LDG prefetch.
// ---------------------------------------------------------------------------
__global__ __launch_bounds__(64) void scan_phase2()
{
    const int n   = blockIdx.x;
    const int tid = threadIdx.x;
    const int h   = tid >> 4;
    const int i   = tid & 15;

    __shared__ __align__(16) float Ts[2][HEADS * 256];
    __shared__ __align__(16) float Us[2][HEADS * 256];

    float Sr[16];
#pragma unroll
    for (int j = 0; j < 16; j++) Sr[j] = 0.f;

    {
        const size_t ob = (size_t)(n * NCHUNK) * HEADS * 256;
        const float4* Tg = (const float4*)(g_T + ob);
        const float4* Ug = (const float4*)(g_U + ob);
#pragma unroll
        for (int j = 0; j < 4; j++) {
            ((float4*)Ts[0])[tid + j * 64] = Tg[tid + j * 64];
            ((float4*)Us[0])[tid + j * 64] = Ug[tid + j * 64];
        }
    }
    __syncthreads();

    for (int c = 0; c < NCHUNK; c++) {
        const int cur = c & 1;
        float4 pfT[4], pfU[4];
        if (c + 1 < NCHUNK) {
            const size_t obn = (size_t)(n * NCHUNK + c + 1) * HEADS * 256;
            const float4* Tg = (const float4*)(g_T + obn);
            const float4* Ug = (const float4*)(g_U + obn);
#pragma unroll
            for (int j = 0; j < 4; j++) {
                pfT[j] = Tg[tid + j * 64];
                pfU[j] = Ug[tid + j * 64];
            }
        }

        {
            const size_t ob = (size_t)(n * NCHUNK + c) * HEADS * 256;
            float* Sd = g_S + ob + (size_t)h * 256 + i * 16;
#pragma unroll
            for (int j = 0; j < 4; j++)
                *(float4*)(Sd + 4*j) = make_float4(Sr[4*j], Sr[4*j+1],
                                                   Sr[4*j+2], Sr[4*j+3]);
        }

        u64 Sn2[8];
        const u64* Uh = (const u64*)(Us[cur] + h * 256 + i * 16);
#pragma unroll
        for (int p = 0; p < 8; p++) Sn2[p] = Uh[p];
        const float* Th = Ts[cur] + h * 256;
#pragma unroll
        for (int u = 0; u < 16; u++) {
            u64 su2 = pk2(Sr[u], Sr[u]);
            const u64* Tu = (const u64*)(Th + u * 16);
#pragma unroll
            for (int p = 0; p < 8; p++) Sn2[p] = ffma2(su2, Tu[p], Sn2[p]);
        }
#pragma unroll
        for (int p = 0; p < 8; p++) upk2(Sn2[p], Sr[2*p], Sr[2*p+1]);

        if (c + 1 < NCHUNK) {
#pragma unroll
            for (int j = 0; j < 4; j++) {
                ((float4*)Ts[cur ^ 1])[tid + j * 64] = pfT[j];
                ((float4*)Us[cur ^ 1])[tid + j * 64] = pfU[j];
            }
        }
        __syncthreads();
    }
}

// ---------------------------------------------------------------------------
// Scan pass 3: 32-thread blocks, 2 rows/thread, replay + emit outputs.
// ---------------------------------------------------------------------------
__global__ __launch_bounds__(32) void scan_phase3()
{
    const int n   = blockIdx.x;
    const int c   = blockIdx.y;
    const int tid = threadIdx.x;
    const int h   = tid >> 3;
    const int i2  = tid & 7;
    const int r0  = i2;
    const int r1  = i2 + 8;

    __shared__ __align__(16) float ks[16 * 64];
    __shared__ __align__(16) float qs[16 * 64];
    __shared__ __align__(16) float vs[16 * 64];
    __shared__ float bs[16 * HEADS];
    __shared__ float as_[16 * HEADS];

    u64 Ma[8], Mb[8];
    {
        const size_t ob = ((size_t)(n * NCHUNK + c) * HEADS + h) * 256;
        const u64* S0 = (const u64*)(g_S + ob + r0 * 16);
        const u64* S1 = (const u64*)(g_S + ob + r1 * 16);
#pragma unroll
        for (int p = 0; p < 8; p++) { Ma[p] = S0[p]; Mb[p] = S1[p]; }
    }

    for (int qt = 0; qt < 4; qt++) {
        const size_t base  = ((size_t)n * TLEN + (size_t)c * CCH + qt * 16) * 64;
        const size_t base2 = ((size_t)n * TLEN + (size_t)c * CCH + qt * 16) * HEADS;
        {
            const float4* gk4 = (const float4*)(g_k + base);
            const float4* gq4 = (const float4*)(g_q + base);
            const float4* gv4 = (const float4*)(g_v + base);
#pragma unroll
            for (int idx = tid; idx < 16 * 16; idx += 32) {
                ((float4*)ks)[idx] = gk4[idx];
                ((float4*)qs)[idx] = gq4[idx];
                ((float4*)vs)[idx] = gv4[idx];
            }
#pragma unroll
            for (int idx = tid; idx < 16 * HEADS; idx += 32) {
                bs[idx]  = g_beta[base2 + idx];
                as_[idx] = g_alpha[base2 + idx];
            }
        }
        __syncthreads();

        for (int tt = 0; tt < 16; tt++) {
            const u64* kp2 = (const u64*)(ks + tt * 64 + h * 16);
            u64 k2[8];
#pragma unroll
            for (int p = 0; p < 8; p++) k2[p] = kp2[p];

            float Mka = pdot8(Ma, k2);
            float Mkb = pdot8(Mb, k2);

            float a  = as_[tt * HEADS + h];
            float b  = bs [tt * HEADS + h];
            float va = vs [tt * 64 + h * 16 + r0];
            float vb = vs [tt * 64 + h * 16 + r1];
            float ca = b * va - a * Mka;
            float cb = b * vb - a * Mkb;
            u64 ca2 = pk2(ca, ca), cb2 = pk2(cb, cb);

#pragma unroll
            for (int p = 0; p < 8; p++) {
                Ma[p] = ffma2(k2[p], ca2, Ma[p]);
                Mb[p] = ffma2(k2[p], cb2, Mb[p]);
            }

            const u64* qp2 = (const u64*)(qs + tt * 64 + h * 16);
            u64 q2[8];
#pragma unroll
            for (int p = 0; p < 8; p++) q2[p] = qp2[p];
            float oa  = pdot8(Ma, q2);
            float ob_ = pdot8(Mb, q2);

            g_o[base + tt * 64 + h * 16 + r0] = oa;
            g_o[base + tt * 64 + h * 16 + r1] = ob_;
        }
        __syncthreads();
    }
}

// ---------------------------------------------------------------------------
// Kernel D (tf32 tensor): fib = o @ out_w^T + out_b, scatter to (B,T,P,K).
// ---------------------------------------------------------------------------
#define ASTR 36
#define BSTR 68

__global__ __launch_bounds__(128) void gemmD_kernel(const float* __restrict__ ob,
                                                    float* __restrict__ out)
{
    __shared__ __align__(16) float As2[128][ASTR];
    __shared__ __align__(16) float Bs2[32][BSTR];

    const int tid  = threadIdx.x;
    const int lane = tid & 31;
    const int wid  = tid >> 5;
    const int g    = lane >> 2;
    const int t    = lane & 3;
    const int wm   = (wid >> 1) * 64;
    const int wn   = (wid & 1) * 32;
    const int m0   = blockIdx.y * 128;
    const int n0   = blockIdx.x * 64;

    float acc[4][4][4];
#pragma unroll
    for (int i = 0; i < 4; i++)
#pragma unroll
        for (int j = 0; j < 4; j++)
#pragma unroll
            for (int r = 0; r < 4; r++) acc[i][j][r] = 0.f;

    for (int k0 = 0; k0 < 64; k0 += 32) {
#pragma unroll
        for (int i = 0; i < 8; i++) {
            int e   = i * 128 + tid;
            int row = e >> 3;
            int cq  = (e & 7) * 4;
            float4 av = *(const float4*)(g_o + (size_t)(m0 + row) * 64 + k0 + cq);
            float4 tv = make_float4(tf32r(av.x), tf32r(av.y), tf32r(av.z), tf32r(av.w));
            *(float4*)&As2[row][cq] = tv;
        }
#pragma unroll
        for (int i = 0; i < 4; i++) {
            int e  = i * 128 + tid;
            int kk = e >> 4;
            int cq = (e & 15) * 4;
            float4 bv = *(const float4*)(g_Bpack2 + (size_t)(k0 + kk) * KOUT + n0 + cq);
            *(float4*)&Bs2[kk][cq] = bv;
        }
        __syncthreads();

#pragma unroll
        for (int ks = 0; ks < 4; ks++) {
            const int kb = ks * 8;
            unsigned a[4][4], b[4][2];
#pragma unroll
            for (int mt = 0; mt < 4; mt++) {
                int r = wm + mt * 16 + g;
                a[mt][0] = fu(As2[r][kb + t]);
                a[mt][1] = fu(As2[r + 8][kb + t]);
                a[mt][2] = fu(As2[r][kb + t + 4]);
                a[mt][3] = fu(As2[r + 8][kb + t + 4]);
            }
#pragma unroll
            for (int nt = 0; nt < 4; nt++) {
                int n = wn + nt * 8 + g;
                b[nt][0] = fu(Bs2[kb + t][n]);
                b[nt][1] = fu(Bs2[kb + t + 4][n]);
            }
#pragma unroll
            for (int mt = 0; mt < 4; mt++)
#pragma unroll
                for (int nt = 0; nt < 4; nt++)
                    MMA_TF32(acc[mt][nt], a[mt], b[nt]);
        }
        __syncthreads();
    }

    const int nseq = m0 >> 11;
    const int tb   = m0 & 2047;
    const int bb   = nseq >> 4;
    const int pp   = nseq & 15;
#pragma unroll
    for (int mt = 0; mt < 4; mt++) {
#pragma unroll
        for (int nt = 0; nt < 4; nt++) {
            int r   = wm + mt * 16 + g;
            int col = n0 + wn + nt * 8 + 2 * t;
            float b0 = ob[col], b1 = ob[col + 1];
            int t1 = tb + r;
            size_t d1 = (((size_t)bb * TLEN + t1) * 16 + pp) * KOUT + col;
            *(float2*)(out + d1) = make_float2(acc[mt][nt][0] + b0,
                                               acc[mt][nt][1] + b1);
            int t2 = t1 + 8;
            size_t d2 = (((size_t)bb * TLEN + t2) * 16 + pp) * KOUT + col;
            *(float2*)(out + d2) = make_float2(acc[mt][nt][2] + b0,
                                               acc[mt][nt][3] + b1);
        }
    }
}

// ---------------------------------------------------------------------------
// launch
// ---------------------------------------------------------------------------
extern "C" void kernel_launch(void* const* d_in, const int* in_sizes, int n_in,
                              void* d_out, int out_size)
{
    const float* joint = (const float*)d_in[0];
    const float* curv  = (const float*)d_in[1];
    const float* ent   = (const float*)d_in[2];
    const float* Wq    = (const float*)d_in[3];
    const float* Wk    = (const float*)d_in[4];
    const float* Wv    = (const float*)d_in[5];
    const float* Wbw   = (const float*)d_in[6];
    const float* Wbb   = (const float*)d_in[7];
    const float* Waw   = (const float*)d_in[8];
    const float* Wab   = (const float*)d_in[9];
    const float* cw    = (const float*)d_in[10];
    const float* ew    = (const float*)d_in[11];
    const float* out_w = (const float*)d_in[12];
    const float* out_b = (const float*)d_in[13];
    const float* lqw   = (const float*)d_in[14];
    const float* lqb   = (const float*)d_in[15];
    const float* lkw   = (const float*)d_in[16];
    const float* lkb   = (const float*)d_in[17];
    float* out = (float*)d_out;

    pack_kernel<<<256, 256>>>(Wq, Wk, Wv, out_w);

    gemmA_kernel<<<dim3(3, M_TOK / 128), 128>>>(joint, lqw, lqb, lkw, lkb);

    beta_kernel<<<M_TOK / 8, 256>>>(joint, curv, ent, Wbw, Wbb, Waw, Wab, cw, ew);

    scan_phase1<<<dim3(NSEQ, NCHUNK), 32>>>();
    scan_phase2<<<NSEQ, 64>>>();
    scan_phase3<<<dim3(NSEQ, NCHUNK), 32>>>();

    gemmD_kernel<<<dim3(KOUT / 64, M_TOK / 128), 128>>>(out_b, out);
}

// round 12
// speedup vs baseline: 1.4439x; 1.1651x over previous
#include <cuda_runtime.h>
#include <cuda_bf16.h>
#include <math.h>

// ---------------------------------------------------------------------------
// B=4, T=2048, P=16, J=256, H=4, D=16, MEM=64, K_OUT=192
// N = 64 sequences; tokens M_TOK = 131072
// gemmA (tf32, cp.async): q->LN->g_q, k->LN+L2->g_k (in-register), v->g_v,
// beta/alpha fused into the v block (extra n=8 MMA). Chunked scan CCH=32.
// gemmD (tf32, cp.async) + scatter.
// ---------------------------------------------------------------------------

#define M_TOK   131072
#define JDIM    256
#define NPRE    192
#define NSEQ    64
#define TLEN    2048
#define HEADS   4
#define KOUT    192
#define CCH     32
#define NCHUNK  (TLEN / CCH)    // 64

typedef unsigned long long u64;

// -------- scratch (device globals; no allocation allowed) --------
__device__ float g_Bpack [(size_t)JDIM * NPRE];
__device__ float g_Bpack2[(size_t)64 * KOUT];
__device__ float g_Bpack3[(size_t)JDIM * 8];        // beta(4)/alpha(4) weights
__device__ float g_q     [(size_t)M_TOK * 64];
__device__ float g_k     [(size_t)M_TOK * 64];
__device__ float g_v     [(size_t)M_TOK * 64];
__device__ float g_beta  [(size_t)M_TOK * HEADS];
__device__ float g_alpha [(size_t)M_TOK * HEADS];
__device__ float g_o     [(size_t)M_TOK * 64];
__device__ float g_T [(size_t)NSEQ * NCHUNK * HEADS * 256];
__device__ float g_U [(size_t)NSEQ * NCHUNK * HEADS * 256];
__device__ float g_S [(size_t)NSEQ * NCHUNK * HEADS * 256];

// ---- helpers ----
__device__ __forceinline__ float tf32r(float x)
{
    unsigned u;
    asm("cvt.rna.tf32.f32 %0, %1;" : "=r"(u) : "f"(x));
    return __uint_as_float(u);
}
__device__ __forceinline__ unsigned fu(float x) { return __float_as_uint(x); }
__device__ __forceinline__ unsigned futf(float x)
{
    unsigned u;
    asm("cvt.rna.tf32.f32 %0, %1;" : "=r"(u) : "f"(x));
    return u;
}

__device__ __forceinline__ u64 pk2(float lo, float hi)
{
    u64 r;
    asm("mov.b64 %0, {%1, %2};" : "=l"(r) : "f"(lo), "f"(hi));
    return r;
}
__device__ __forceinline__ void upk2(u64 v, float& lo, float& hi)
{
    asm("mov.b64 {%0, %1}, %2;" : "=f"(lo), "=f"(hi) : "l"(v));
}
__device__ __forceinline__ u64 ffma2(u64 a, u64 b, u64 c)
{
    u64 d;
    asm("fma.rn.f32x2 %0, %1, %2, %3;" : "=l"(d) : "l"(a), "l"(b), "l"(c));
    return d;
}
__device__ __forceinline__ float pdot8(const u64* r, const u64* k)
{
    u64 a0 = 0ull, a1 = 0ull;
#pragma unroll
    for (int p = 0; p < 4; p++) {
        a0 = ffma2(r[p],     k[p],     a0);
        a1 = ffma2(r[p + 4], k[p + 4], a1);
    }
    float x0, x1, y0, y1;
    upk2(a0, x0, x1); upk2(a1, y0, y1);
    return (x0 + x1) + (y0 + y1);
}

__device__ __forceinline__ unsigned su32(const void* p)
{
    return (unsigned)__cvta_generic_to_shared(p);
}
#define CP16(dst, src) \
    asm volatile("cp.async.cg.shared.global [%0], [%1], 16;" :: "r"(dst), "l"(src))
#define CP_COMMIT() asm volatile("cp.async.commit_group;")
#define CP_WAIT1()  asm volatile("cp.async.wait_group 1;")
#define CP_WAIT0()  asm volatile("cp.async.wait_group 0;")

#define MMA_TF32(c, a, b)                                                     \
    asm volatile("mma.sync.aligned.m16n8k8.row.col.f32.tf32.tf32.f32 "        \
                 "{%0,%1,%2,%3}, {%4,%5,%6,%7}, {%8,%9}, {%0,%1,%2,%3};"      \
                 : "+f"((c)[0]), "+f"((c)[1]), "+f"((c)[2]), "+f"((c)[3])     \
                 : "r"((a)[0]), "r"((a)[1]), "r"((a)[2]), "r"((a)[3]),        \
                   "r"((b)[0]), "r"((b)[1]))

__device__ __forceinline__ float qred(float x)
{
    x += __shfl_xor_sync(0xffffffffu, x, 1);
    x += __shfl_xor_sync(0xffffffffu, x, 2);
    return x;
}
__device__ __forceinline__ float sigm(float x) { return 1.f / (1.f + expf(-x)); }

// ---------------------------------------------------------------------------
// Kernel 0: pack weights (k-major) + round to tf32
// ---------------------------------------------------------------------------
__global__ void pack_kernel(const float* __restrict__ Wq,
                            const float* __restrict__ Wk,
                            const float* __restrict__ Wv,
                            const float* __restrict__ out_w,
                            const float* __restrict__ Wbw,
                            const float* __restrict__ Waw)
{
    int idx = blockIdx.x * blockDim.x + threadIdx.x;
    if (idx < JDIM * NPRE) {
        int k = idx / NPRE;
        int o = idx - k * NPRE;
        float val;
        if      (o < 64)  val = Wq[(size_t)o       * JDIM + k];
        else if (o < 128) val = Wk[(size_t)(o-64)  * JDIM + k];
        else              val = Wv[(size_t)(o-128) * JDIM + k];
        g_Bpack[idx] = tf32r(val);
    }
    int idx2 = idx - JDIM * NPRE;
    if (idx2 >= 0 && idx2 < 64 * KOUT) {
        int k = idx2 / KOUT;
        int o = idx2 - k * KOUT;
        g_Bpack2[idx2] = tf32r(out_w[(size_t)o * 64 + k]);
    }
    int idx3 = idx2 - 64 * KOUT;
    if (idx3 >= 0 && idx3 < JDIM * 8) {
        int k = idx3 >> 3;
        int o = idx3 & 7;
        float val = (o < 4) ? Wbw[(size_t)o * JDIM + k]
                            : Waw[(size_t)(o - 4) * JDIM + k];
        g_Bpack3[idx3] = tf32r(val);
    }
}

// ---------------------------------------------------------------------------
// Kernel A: tf32 GEMM, BM=128 BN=64 BK=16, cp.async 2-stage, 128 threads.
// bx=0: q -> fused LN -> g_q ; bx=1: k -> LN+L2 -> g_k ;
// bx=2: v -> g_v + fused beta/alpha (extra n=8 MMA on wn==0 warps).
// ---------------------------------------------------------------------------
#define A_KS  20
#define B_KS  68

__global__ __launch_bounds__(128) void gemmA_kernel(
    const float* __restrict__ A,
    const float* __restrict__ lqw, const float* __restrict__ lqb,
    const float* __restrict__ lkw, const float* __restrict__ lkb,
    const float* __restrict__ curv, const float* __restrict__ ent,
    const float* __restrict__ Wbb,  const float* __restrict__ Wab,
    const float* __restrict__ cw,   const float* __restrict__ ew)
{
    __shared__ __align__(16) float As[2][128][A_KS];
    __shared__ __align__(16) float Bs[2][16][B_KS];
    __shared__ __align__(16) float Bs3[2][16][8];

    const int tid  = threadIdx.x;
    const int lane = tid & 31;
    const int wid  = tid >> 5;
    const int g    = lane >> 2;
    const int t    = lane & 3;
    const int wm   = (wid >> 1) * 64;
    const int wn   = (wid & 1) * 32;
    const int bx   = blockIdx.x;
    const int m0   = blockIdx.y * 128;
    const int n0   = bx * 64;
    const bool do_ba = (bx == 2) && (wn == 0);

    float acc[4][4][4];
#pragma unroll
    for (int i = 0; i < 4; i++)
#pragma unroll
        for (int j = 0; j < 4; j++)
#pragma unroll
            for (int r = 0; r < 4; r++) acc[i][j][r] = 0.f;
    float accB[4][4];
#pragma unroll
    for (int i = 0; i < 4; i++)
#pragma unroll
        for (int r = 0; r < 4; r++) accB[i][r] = 0.f;

    auto load_tiles = [&](int k0, int buf) {
#pragma unroll
        for (int i = 0; i < 4; i++) {
            int e   = i * 128 + tid;
            int row = e >> 2;
            int cq  = (e & 3) * 4;
            CP16(su32(&As[buf][row][cq]),
                 A + (size_t)(m0 + row) * JDIM + k0 + cq);
        }
#pragma unroll
        for (int i = 0; i < 2; i++) {
            int e  = i * 128 + tid;
            int kk = e >> 4;
            int cq = (e & 15) * 4;
            CP16(su32(&Bs[buf][kk][cq]),
                 g_Bpack + (size_t)(k0 + kk) * NPRE + n0 + cq);
        }
        if (bx == 2 && tid < 32) {
            int kk = tid >> 1;
            int cq = (tid & 1) * 4;
            CP16(su32(&Bs3[buf][kk][cq]),
                 g_Bpack3 + (size_t)(k0 + kk) * 8 + cq);
        }
    };

    load_tiles(0, 0);
    CP_COMMIT();

    for (int kt = 0; kt < 16; kt++) {
        const int cur = kt & 1;
        if (kt < 15) {
            load_tiles((kt + 1) * 16, cur ^ 1);
            CP_COMMIT();
            CP_WAIT1();
        } else {
            CP_WAIT0();
        }
        __syncthreads();

#pragma unroll
        for (int ks = 0; ks < 2; ks++) {
            const int kb = ks * 8;
            unsigned a[4][4], b[4][2];
#pragma unroll
            for (int mt = 0; mt < 4; mt++) {
                int r = wm + mt * 16 + g;
                a[mt][0] = futf(As[cur][r][kb + t]);
                a[mt][1] = futf(As[cur][r + 8][kb + t]);
                a[mt][2] = futf(As[cur][r][kb + t + 4]);
                a[mt][3] = futf(As[cur][r + 8][kb + t + 4]);
            }
#pragma unroll
            for (int nt = 0; nt < 4; nt++) {
                int n = wn + nt * 8 + g;
                b[nt][0] = fu(Bs[cur][kb + t][n]);
                b[nt][1] = fu(Bs[cur][kb + t + 4][n]);
            }
#pragma unroll
            for (int mt = 0; mt < 4; mt++)
#pragma unroll
                for (int nt = 0; nt < 4; nt++)
                    MMA_TF32(acc[mt][nt], a[mt], b[nt]);
            if (do_ba) {
                unsigned b3[2];
                b3[0] = fu(Bs3[cur][kb + t][g]);
                b3[1] = fu(Bs3[cur][kb + t + 4][g]);
#pragma unroll
                for (int mt = 0; mt < 4; mt++)
                    MMA_TF32(accB[mt], a[mt], b3);
            }
        }
        __syncthreads();
    }

    if (bx == 2) {
        // v: direct store
#pragma unroll
        for (int mt = 0; mt < 4; mt++) {
#pragma unroll
            for (int nt = 0; nt < 4; nt++) {
                int row = m0 + wm + mt * 16 + g;
                int col = wn + nt * 8 + 2 * t;
                *(float2*)(g_v + (size_t)row * 64 + col) =
                    make_float2(acc[mt][nt][0], acc[mt][nt][1]);
                *(float2*)(g_v + (size_t)(row + 8) * 64 + col) =
                    make_float2(acc[mt][nt][2], acc[mt][nt][3]);
            }
        }
        // beta/alpha epilogue (wn==0 warps). Thread cols: 2t, 2t+1 in 0..7.
        if (do_ba) {
            const int bidx = m0 >> 15;              // batch = row / (P*T)
            const float Kv = fminf(fabsf(curv[bidx]), 10.f);
            const float Sv = fminf(fmaxf(ent[bidx], 0.f), 5.f);
            const int c0 = 2 * t, c1 = 2 * t + 1;
            const bool isA = (t >= 2);
            const int h0 = isA ? c0 - 4 : c0;
            const int h1 = isA ? c1 - 4 : c1;
            const float off0 = isA ? Wab[h0] : Wbb[h0];
            const float off1 = isA ? Wab[h1] : Wbb[h1];
            const float mod0 = isA ? Sv * ew[h0] : Kv * cw[h0];
            const float mod1 = isA ? Sv * ew[h1] : Kv * cw[h1];
            float* dstba = isA ? g_alpha : g_beta;
#pragma unroll
            for (int mt = 0; mt < 4; mt++) {
#pragma unroll
                for (int half = 0; half < 2; half++) {
                    int row = m0 + wm + mt * 16 + g + half * 8;
                    float p0 = accB[mt][half * 2 + 0];
                    float p1 = accB[mt][half * 2 + 1];
                    dstba[(size_t)row * HEADS + h0] = sigm(sigm(p0 + off0) + mod0);
                    dstba[(size_t)row * HEADS + h1] = sigm(sigm(p1 + off1) + mod1);
                }
            }
        }
        return;
    }

    // q/k: fused LayerNorm (+L2 for k) via quad butterflies.
    const float* wp = (bx == 0) ? lqw : lkw;
    const float* bp = (bx == 0) ? lqb : lkb;
    float wv0 = wp[2 * t], wv1 = wp[2 * t + 1];
    float wv2 = wp[8 + 2 * t], wv3 = wp[8 + 2 * t + 1];
    float bb0 = bp[2 * t], bb1 = bp[2 * t + 1];
    float bb2 = bp[8 + 2 * t], bb3 = bp[8 + 2 * t + 1];
    float* dst = (bx == 0) ? g_q : g_k;
    const float inv16 = 1.f / 16.f;

#pragma unroll
    for (int mt = 0; mt < 4; mt++) {
#pragma unroll
        for (int hl = 0; hl < 2; hl++) {
            const int nt0 = 2 * hl, nt1 = 2 * hl + 1;
#pragma unroll
            for (int half = 0; half < 2; half++) {
                const int c0 = half * 2, c1 = half * 2 + 1;
                float x0 = acc[mt][nt0][c0], x1 = acc[mt][nt0][c1];
                float x2 = acc[mt][nt1][c0], x3 = acc[mt][nt1][c1];
                float mu = qred(x0 + x1 + x2 + x3) * inv16;
                float d0 = x0 - mu, d1 = x1 - mu, d2 = x2 - mu, d3 = x3 - mu;
                float var = qred(d0*d0 + d1*d1 + d2*d2 + d3*d3) * inv16;
                float rs = 1.f / sqrtf(var + 1e-5f);
                float n0v = d0 * rs * wv0 + bb0;
                float n1v = d1 * rs * wv1 + bb1;
                float n2v = d2 * rs * wv2 + bb2;
                float n3v = d3 * rs * wv3 + bb3;
                if (bx == 1) {
                    float ss = qred(n0v*n0v + n1v*n1v + n2v*n2v + n3v*n3v);
                    float sc = 1.f / fmaxf(sqrtf(ss), 1e-12f);
                    n0v *= sc; n1v *= sc; n2v *= sc; n3v *= sc;
                }
                int row = m0 + wm + mt * 16 + g + half * 8;
                int cb  = wn + hl * 16 + 2 * t;
                *(float2*)(dst + (size_t)row * 64 + cb)     = make_float2(n0v, n1v);
                *(float2*)(dst + (size_t)row * 64 + cb + 8) = make_float2(n2v, n3v);
            }
        }
    }
}

// ---------------------------------------------------------------------------
// Scan pass 1 (CCH=32): 32-thread blocks, thread (h,i2) owns rows i2, i2+8.
// ---------------------------------------------------------------------------
__global__ __launch_bounds__(32) void scan_phase1()
{
    const int n   = blockIdx.x;
    const int c   = blockIdx.y;
    const int tid = threadIdx.x;
    const int h   = tid >> 3;
    const int i2  = tid & 7;
    const int r0  = i2;
    const int r1  = i2 + 8;

    __shared__ __align__(16) float ks[CCH * 64];
    __shared__ __align__(16) float vs[CCH * 64];
    __shared__ float bs[CCH * HEADS];
    __shared__ float as_[CCH * HEADS];

    u64 Ta[8], Tb[8], Ua[8], Ub[8];
#pragma unroll
    for (int p = 0; p < 8; p++) {
        Ta[p] = pk2((2*p == r0) ? 1.f : 0.f, (2*p+1 == r0) ? 1.f : 0.f);
        Tb[p] = pk2((2*p == r1) ? 1.f : 0.f, (2*p+1 == r1) ? 1.f : 0.f);
        Ua[p] = 0ull; Ub[p] = 0ull;
    }

    const size_t base  = ((size_t)n * TLEN + (size_t)c * CCH) * 64;
    const size_t base2 = ((size_t)n * TLEN + (size_t)c * CCH) * HEADS;
    {
        const float4* gk4 = (const float4*)(g_k + base);
        const float4* gv4 = (const float4*)(g_v + base);
#pragma unroll
        for (int idx = tid; idx < CCH * 16; idx += 32) {
            ((float4*)ks)[idx] = gk4[idx];
            ((float4*)vs)[idx] = gv4[idx];
        }
#pragma unroll
        for (int idx = tid; idx < CCH * HEADS; idx += 32) {
            bs[idx]  = g_beta[base2 + idx];
            as_[idx] = g_alpha[base2 + idx];
        }
    }
    __syncthreads();

    for (int tt = 0; tt < CCH; tt++) {
        const u64* kp2 = (const u64*)(ks + tt * 64 + h * 16);
        u64 k2[8];
#pragma unroll
        for (int p = 0; p < 8; p++) k2[p] = kp2[p];

        float Tka = pdot8(Ta, k2);
        float Tkb = pdot8(Tb, k2);
        float Uka = pdot8(Ua, k2);
        float Ukb = pdot8(Ub, k2);

        float a  = as_[tt * HEADS + h];
        float b  = bs [tt * HEADS + h];
        float va = vs [tt * 64 + h * 16 + r0];
        float vb = vs [tt * 64 + h * 16 + r1];
        float cTa = -a * Tka, cTb = -a * Tkb;
        float cUa = b * va - a * Uka;
        float cUb = b * vb - a * Ukb;
        u64 cTa2 = pk2(cTa, cTa), cTb2 = pk2(cTb, cTb);
        u64 cUa2 = pk2(cUa, cUa), cUb2 = pk2(cUb, cUb);

#pragma unroll
        for (int p = 0; p < 8; p++) {
            Ta[p] = ffma2(k2[p], cTa2, Ta[p]);
            Tb[p] = ffma2(k2[p], cTb2, Tb[p]);
            Ua[p] = ffma2(k2[p], cUa2, Ua[p]);
            Ub[p] = ffma2(k2[p], cUb2, Ub[p]);
        }
    }

    const size_t ob = ((size_t)(n * NCHUNK + c) * HEADS + h) * 256;
    u64* Td0 = (u64*)(g_T + ob + r0 * 16);
    u64* Td1 = (u64*)(g_T + ob + r1 * 16);
    u64* Ud0 = (u64*)(g_U + ob + r0 * 16);
    u64* Ud1 = (u64*)(g_U + ob + r1 * 16);
#pragma unroll
    for (int p = 0; p < 8; p++) {
        Td0[p] = Ta[p]; Td1[p] = Tb[p];
        Ud0[p] = Ua[p]; Ud1[p] = Ub[p];
    }
}

// ---------------------------------------------------------------------------
// Scan pass 2: compose chunk operators per (n,h) with LDG prefetch.
// ---------------------------------------------------------------------------
__global__ __launch_bounds__(64) void scan_phase2()
{
    const int n   = blockIdx.x;
    const int tid = threadIdx.x;
    const int h   = tid >> 4;
    const int i   = tid & 15;

    __shared__ __align__(16) float Ts[2][HEADS * 256];
    __shared__ __align__(16) float Us[2][HEADS * 256];

    float Sr[16];
#pragma unroll
    for (int j = 0; j < 16; j++) Sr[j] = 0.f;

    {
        const size_t ob = (size_t)(n * NCHUNK) * HEADS * 256;
        const float4* Tg = (const float4*)(g_T + ob);
        const float4* Ug = (const float4*)(g_U + ob);
#pragma unroll
        for (int j = 0; j < 4; j++) {
            ((float4*)Ts[0])[tid + j * 64] = Tg[tid + j * 64];
            ((float4*)Us[0])[tid + j * 64] = Ug[tid + j * 64];
        }
    }
    __syncthreads();

    for (int c = 0; c < NCHUNK; c++) {
        const int cur = c & 1;
        float4 pfT[4], pfU[4];
        if (c + 1 < NCHUNK) {
            const size_t obn = (size_t)(n * NCHUNK + c + 1) * HEADS * 256;
            const float4* Tg = (const float4*)(g_T + obn);
            const float4* Ug = (const float4*)(g_U + obn);
#pragma unroll
            for (int j = 0; j < 4; j++) {
                pfT[j] = Tg[tid + j * 64];
                pfU[j] = Ug[tid + j * 64];
            }
        }

        {
            const size_t ob = (size_t)(n * NCHUNK + c) * HEADS * 256;
            float* Sd = g_S + ob + (size_t)h * 256 + i * 16;
#pragma unroll
            for (int j = 0; j < 4; j++)
                *(float4*)(Sd + 4*j) = make_float4(Sr[4*j], Sr[4*j+1],
                                                   Sr[4*j+2], Sr[4*j+3]);
        }

        u64 Sn2[8];
        const u64* Uh = (const u64*)(Us[cur] + h * 256 + i * 16);
#pragma unroll
        for (int p = 0; p < 8; p++) Sn2[p] = Uh[p];
        const float* Th = Ts[cur] + h * 256;
#pragma unroll
        for (int u = 0; u < 16; u++) {
            u64 su2 = pk2(Sr[u], Sr[u]);
            const u64* Tu = (const u64*)(Th + u * 16);
#pragma unroll
            for (int p = 0; p < 8; p++) Sn2[p] = ffma2(su2, Tu[p], Sn2[p]);
        }
#pragma unroll
        for (int p = 0; p < 8; p++) upk2(Sn2[p], Sr[2*p], Sr[2*p+1]);

        if (c + 1 < NCHUNK) {
#pragma unroll
            for (int j = 0; j < 4; j++) {
                ((float4*)Ts[cur ^ 1])[tid + j * 64] = pfT[j];
                ((float4*)Us[cur ^ 1])[tid + j * 64] = pfU[j];
            }
        }
        __syncthreads();
    }
}

// ---------------------------------------------------------------------------
// Scan pass 3 (CCH=32): 32-thread blocks, 2 rows/thread, replay + outputs.
// ---------------------------------------------------------------------------
__global__ __launch_bounds__(32) void scan_phase3()
{
    const int n   = blockIdx.x;
    const int c   = blockIdx.y;
    const int tid = threadIdx.x;
    const int h   = tid >> 3;
    const int i2  = tid & 7;
    const int r0  = i2;
    const int r1  = i2 + 8;

    __shared__ __align__(16) float ks[16 * 64];
    __shared__ __align__(16) float qs[16 * 64];
    __shared__ __align__(16) float vs[16 * 64];
    __shared__ float bs[16 * HEADS];
    __shared__ float as_[16 * HEADS];

    u64 Ma[8], Mb[8];
    {
        const size_t ob = ((size_t)(n * NCHUNK + c) * HEADS + h) * 256;
        const u64* S0 = (const u64*)(g_S + ob + r0 * 16);
        const u64* S1 = (const u64*)(g_S + ob + r1 * 16);
#pragma unroll
        for (int p = 0; p < 8; p++) { Ma[p] = S0[p]; Mb[p] = S1[p]; }
    }

    for (int qt = 0; qt < 2; qt++) {
        const size_t base  = ((size_t)n * TLEN + (size_t)c * CCH + qt * 16) * 64;
        const size_t base2 = ((size_t)n * TLEN + (size_t)c * CCH + qt * 16) * HEADS;
        {
            const float4* gk4 = (const float4*)(g_k + base);
            const float4* gq4 = (const float4*)(g_q + base);
            const float4* gv4 = (const float4*)(g_v + base);
#pragma unroll
            for (int idx = tid; idx < 16 * 16; idx += 32) {
                ((float4*)ks)[idx] = gk4[idx];
                ((float4*)qs)[idx] = gq4[idx];
                ((float4*)vs)[idx] = gv4[idx];
            }
#pragma unroll
            for (int idx = tid; idx < 16 * HEADS; idx += 32) {
                bs[idx]  = g_beta[base2 + idx];
                as_[idx] = g_alpha[base2 + idx];
            }
        }
        __syncthreads();

        for (int tt = 0; tt < 16; tt++) {
            const u64* kp2 = (const u64*)(ks + tt * 64 + h * 16);
            u64 k2[8];
#pragma unroll
            for (int p = 0; p < 8; p++) k2[p] = kp2[p];

            float Mka = pdot8(Ma, k2);
            float Mkb = pdot8(Mb, k2);

            float a  = as_[tt * HEADS + h];
            float b  = bs [tt * HEADS + h];
            float va = vs [tt * 64 + h * 16 + r0];
            float vb = vs [tt * 64 + h * 16 + r1];
            float ca = b * va - a * Mka;
            float cb = b * vb - a * Mkb;
            u64 ca2 = pk2(ca, ca), cb2 = pk2(cb, cb);

#pragma unroll
            for (int p = 0; p < 8; p++) {
                Ma[p] = ffma2(k2[p], ca2, Ma[p]);
                Mb[p] = ffma2(k2[p], cb2, Mb[p]);
            }

            const u64* qp2 = (const u64*)(qs + tt * 64 + h * 16);
            u64 q2[8];
#pragma unroll
            for (int p = 0; p < 8; p++) q2[p] = qp2[p];
            float oa  = pdot8(Ma, q2);
            float ob_ = pdot8(Mb, q2);

            g_o[base + tt * 64 + h * 16 + r0] = oa;
            g_o[base + tt * 64 + h * 16 + r1] = ob_;
        }
        __syncthreads();
    }
}

// ---------------------------------------------------------------------------
// Kernel D (tf32, cp.async 2-stage, BK=16): fib = o @ out_w^T + out_b,
// scatter to (B,T,P,K).
// ---------------------------------------------------------------------------
__global__ __launch_bounds__(128) void gemmD_kernel(const float* __restrict__ ob,
                                                    float* __restrict__ out)
{
    __shared__ __align__(16) float As[2][128][A_KS];
    __shared__ __align__(16) float Bs[2][16][B_KS];

    const int tid  = threadIdx.x;
    const int lane = tid & 31;
    const int wid  = tid >> 5;
    const int g    = lane >> 2;
    const int t    = lane & 3;
    const int wm   = (wid >> 1) * 64;
    const int wn   = (wid & 1) * 32;
    const int m0   = blockIdx.y * 128;
    const int n0   = blockIdx.x * 64;

    float acc[4][4][4];
#pragma unroll
    for (int i = 0; i < 4; i++)
#pragma unroll
        for (int j = 0; j < 4; j++)
#pragma unroll
            for (int r = 0; r < 4; r++) acc[i][j][r] = 0.f;

    auto load_tiles = [&](int k0, int buf) {
#pragma unroll
        for (int i = 0; i < 4; i++) {
            int e   = i * 128 + tid;
            int row = e >> 2;
            int cq  = (e & 3) * 4;
            CP16(su32(&As[buf][row][cq]),
                 g_o + (size_t)(m0 + row) * 64 + k0 + cq);
        }
#pragma unroll
        for (int i = 0; i < 2; i++) {
            int e  = i * 128 + tid;
            int kk = e >> 4;
            int cq = (e & 15) * 4;
            CP16(su32(&Bs[buf][kk][cq]),
                 g_Bpack2 + (size_t)(k0 + kk) * KOUT + n0 + cq);
        }
    };

    load_tiles(0, 0);
    CP_COMMIT();

    for (int kt = 0; kt < 4; kt++) {
        const int cur = kt & 1;
        if (kt < 3) {
            load_tiles((kt + 1) * 16, cur ^ 1);
            CP_COMMIT();
            CP_WAIT1();
        } else {
            CP_WAIT0();
        }
        __syncthreads();

#pragma unroll
        for (int ks = 0; ks < 2; ks++) {
            const int kb = ks * 8;
            unsigned a[4][4], b[4][2];
#pragma unroll
            for (int mt = 0; mt < 4; mt++) {
                int r = wm + mt * 16 + g;
                a[mt][0] = futf(As[cur][r][kb + t]);
                a[mt][1] = futf(As[cur][r + 8][kb + t]);
                a[mt][2] = futf(As[cur][r][kb + t + 4]);
                a[mt][3] = futf(As[cur][r + 8][kb + t + 4]);
            }
#pragma unroll
            for (int nt = 0; nt < 4; nt++) {
                int n = wn + nt * 8 + g;
                b[nt][0] = fu(Bs[cur][kb + t][n]);
                b[nt][1] = fu(Bs[cur][kb + t + 4][n]);
            }
#pragma unroll
            for (int mt = 0; mt < 4; mt++)
#pragma unroll
                for (int nt = 0; nt < 4; nt++)
                    MMA_TF32(acc[mt][nt], a[mt], b[nt]);
        }
        __syncthreads();
    }

    const int nseq = m0 >> 11;
    const int tb   = m0 & 2047;
    const int bb   = nseq >> 4;
    const int pp   = nseq & 15;
#pragma unroll
    for (int mt = 0; mt < 4; mt++) {
#pragma unroll
        for (int nt = 0; nt < 4; nt++) {
            int r   = wm + mt * 16 + g;
            int col = n0 + wn + nt * 8 + 2 * t;
            float b0 = ob[col], b1 = ob[col + 1];
            int t1 = tb + r;
            size_t d1 = (((size_t)bb * TLEN + t1) * 16 + pp) * KOUT + col;
            *(float2*)(out + d1) = make_float2(acc[mt][nt][0] + b0,
                                               acc[mt][nt][1] + b1);
            int t2 = t1 + 8;
            size_t d2 = (((size_t)bb * TLEN + t2) * 16 + pp) * KOUT + col;
            *(float2*)(out + d2) = make_float2(acc[mt][nt][2] + b0,
                                               acc[mt][nt][3] + b1);
        }
    }
}

// ---------------------------------------------------------------------------
// launch
// ---------------------------------------------------------------------------
extern "C" void kernel_launch(void* const* d_in, const int* in_sizes, int n_in,
                              void* d_out, int out_size)
{
    const float* joint = (const float*)d_in[0];
    const float* curv  = (const float*)d_in[1];
    const float* ent   = (const float*)d_in[2];
    const float* Wq    = (const float*)d_in[3];
    const float* Wk    = (const float*)d_in[4];
    const float* Wv    = (const float*)d_in[5];
    const float* Wbw   = (const float*)d_in[6];
    const float* Wbb   = (const float*)d_in[7];
    const float* Waw   = (const float*)d_in[8];
    const float* Wab   = (const float*)d_in[9];
    const float* cw    = (const float*)d_in[10];
    const float* ew    = (const float*)d_in[11];
    const float* out_w = (const float*)d_in[12];
    const float* out_b = (const float*)d_in[13];
    const float* lqw   = (const float*)d_in[14];
    const float* lqb   = (const float*)d_in[15];
    const float* lkw   = (const float*)d_in[16];
    const float* lkb   = (const float*)d_in[17];
    float* out = (float*)d_out;

    pack_kernel<<<256, 256>>>(Wq, Wk, Wv, out_w, Wbw, Waw);

    gemmA_kernel<<<dim3(3, M_TOK / 128), 128>>>(joint, lqw, lqb, lkw, lkb,
                                                curv, ent, Wbb, Wab, cw, ew);

    scan_phase1<<<dim3(NSEQ, NCHUNK), 32>>>();
    scan_phase2<<<NSEQ, 64>>>();
    scan_phase3<<<dim3(NSEQ, NCHUNK), 32>>>();

    gemmD_kernel<<<dim3(KOUT / 64, M_TOK / 128), 128>>>(out_b, out);
}

// round 13
// speedup vs baseline: 1.4747x; 1.0213x over previous
#include <cuda_runtime.h>
#include <cuda_bf16.h>
#include <math.h>

// ---------------------------------------------------------------------------
// B=4, T=2048, P=16, J=256, H=4, D=16, MEM=64, K_OUT=192
// N = 64 sequences; tokens M_TOK = 131072
// gemmA (tf32, cp.async): q->LN->g_q, k->LN+L2->g_k, v->g_v, beta/alpha fused.
// Scan: CCH=32 chunks; phase1 builds chunk ops; phase2a/2b two-level affine
// prefix scan (chain 64 -> 8+8); phase3 reconstructs S and replays.
// gemmD (tf32, cp.async) + scatter.
// ---------------------------------------------------------------------------

#define M_TOK   131072
#define JDIM    256
#define NPRE    192
#define NSEQ    64
#define TLEN    2048
#define HEADS   4
#define KOUT    192
#define CCH     32
#define NCHUNK  (TLEN / CCH)    // 64
#define NGRP    8
#define GCH     (NCHUNK / NGRP) // 8 chunks per group

typedef unsigned long long u64;

// -------- scratch (device globals; no allocation allowed) --------
__device__ float g_Bpack [(size_t)JDIM * NPRE];
__device__ float g_Bpack2[(size_t)64 * KOUT];
__device__ float g_Bpack3[(size_t)JDIM * 8];
__device__ float g_q     [(size_t)M_TOK * 64];
__device__ float g_k     [(size_t)M_TOK * 64];
__device__ float g_v     [(size_t)M_TOK * 64];
__device__ float g_beta  [(size_t)M_TOK * HEADS];
__device__ float g_alpha [(size_t)M_TOK * HEADS];
__device__ float g_o     [(size_t)M_TOK * 64];
__device__ float g_T [(size_t)NSEQ * NCHUNK * HEADS * 256];   // chunk ops -> local prefixes
__device__ float g_U [(size_t)NSEQ * NCHUNK * HEADS * 256];
__device__ float g_GT[(size_t)NSEQ * NGRP * HEADS * 256];     // group totals
__device__ float g_GU[(size_t)NSEQ * NGRP * HEADS * 256];
__device__ float g_G [(size_t)NSEQ * NGRP * HEADS * 256];     // group start states

// ---- helpers ----
__device__ __forceinline__ float tf32r(float x)
{
    unsigned u;
    asm("cvt.rna.tf32.f32 %0, %1;" : "=r"(u) : "f"(x));
    return __uint_as_float(u);
}
__device__ __forceinline__ unsigned fu(float x) { return __float_as_uint(x); }
__device__ __forceinline__ unsigned futf(float x)
{
    unsigned u;
    asm("cvt.rna.tf32.f32 %0, %1;" : "=r"(u) : "f"(x));
    return u;
}

__device__ __forceinline__ u64 pk2(float lo, float hi)
{
    u64 r;
    asm("mov.b64 %0, {%1, %2};" : "=l"(r) : "f"(lo), "f"(hi));
    return r;
}
__device__ __forceinline__ void upk2(u64 v, float& lo, float& hi)
{
    asm("mov.b64 {%0, %1}, %2;" : "=f"(lo), "=f"(hi) : "l"(v));
}
__device__ __forceinline__ u64 ffma2(u64 a, u64 b, u64 c)
{
    u64 d;
    asm("fma.rn.f32x2 %0, %1, %2, %3;" : "=l"(d) : "l"(a), "l"(b), "l"(c));
    return d;
}
__device__ __forceinline__ float pdot8(const u64* r, const u64* k)
{
    u64 a0 = 0ull, a1 = 0ull;
#pragma unroll
    for (int p = 0; p < 4; p++) {
        a0 = ffma2(r[p],     k[p],     a0);
        a1 = ffma2(r[p + 4], k[p + 4], a1);
    }
    float x0, x1, y0, y1;
    upk2(a0, x0, x1); upk2(a1, y0, y1);
    return (x0 + x1) + (y0 + y1);
}

__device__ __forceinline__ unsigned su32(const void* p)
{
    return (unsigned)__cvta_generic_to_shared(p);
}
#define CP16(dst, src) \
    asm volatile("cp.async.cg.shared.global [%0], [%1], 16;" :: "r"(dst), "l"(src))
#define CP_COMMIT() asm volatile("cp.async.commit_group;")
#define CP_WAIT1()  asm volatile("cp.async.wait_group 1;")
#define CP_WAIT0()  asm volatile("cp.async.wait_group 0;")

#define MMA_TF32(c, a, b)                                                     \
    asm volatile("mma.sync.aligned.m16n8k8.row.col.f32.tf32.tf32.f32 "        \
                 "{%0,%1,%2,%3}, {%4,%5,%6,%7}, {%8,%9}, {%0,%1,%2,%3};"      \
                 : "+f"((c)[0]), "+f"((c)[1]), "+f"((c)[2]), "+f"((c)[3])     \
                 : "r"((a)[0]), "r"((a)[1]), "r"((a)[2]), "r"((a)[3]),        \
                   "r"((b)[0]), "r"((b)[1]))

__device__ __forceinline__ float qred(float x)
{
    x += __shfl_xor_sync(0xffffffffu, x, 1);
    x += __shfl_xor_sync(0xffffffffu, x, 2);
    return x;
}
__device__ __forceinline__ float sigm(float x) { return 1.f / (1.f + expf(-x)); }

// ---------------------------------------------------------------------------
// Kernel 0: pack weights (k-major) + round to tf32
// ---------------------------------------------------------------------------
__global__ void pack_kernel(const float* __restrict__ Wq,
                            const float* __restrict__ Wk,
                            const float* __restrict__ Wv,
                            const float* __restrict__ out_w,
                            const float* __restrict__ Wbw,
                            const float* __restrict__ Waw)
{
    int idx = blockIdx.x * blockDim.x + threadIdx.x;
    if (idx < JDIM * NPRE) {
        int k = idx / NPRE;
        int o = idx - k * NPRE;
        float val;
        if      (o < 64)  val = Wq[(size_t)o       * JDIM + k];
        else if (o < 128) val = Wk[(size_t)(o-64)  * JDIM + k];
        else              val = Wv[(size_t)(o-128) * JDIM + k];
        g_Bpack[idx] = tf32r(val);
    }
    int idx2 = idx - JDIM * NPRE;
    if (idx2 >= 0 && idx2 < 64 * KOUT) {
        int k = idx2 / KOUT;
        int o = idx2 - k * KOUT;
        g_Bpack2[idx2] = tf32r(out_w[(size_t)o * 64 + k]);
    }
    int idx3 = idx2 - 64 * KOUT;
    if (idx3 >= 0 && idx3 < JDIM * 8) {
        int k = idx3 >> 3;
        int o = idx3 & 7;
        float val = (o < 4) ? Wbw[(size_t)o * JDIM + k]
                            : Waw[(size_t)(o - 4) * JDIM + k];
        g_Bpack3[idx3] = tf32r(val);
    }
}

// ---------------------------------------------------------------------------
// Kernel A: tf32 GEMM, BM=128 BN=64 BK=16, cp.async 2-stage, 128 threads.
// bx=0: q -> LN -> g_q ; bx=1: k -> LN+L2 -> g_k ;
// bx=2: v -> g_v + fused beta/alpha.
// ---------------------------------------------------------------------------
#define A_KS  20
#define B_KS  68

__global__ __launch_bounds__(128) void gemmA_kernel(
    const float* __restrict__ A,
    const float* __restrict__ lqw, const float* __restrict__ lqb,
    const float* __restrict__ lkw, const float* __restrict__ lkb,
    const float* __restrict__ curv, const float* __restrict__ ent,
    const float* __restrict__ Wbb,  const float* __restrict__ Wab,
    const float* __restrict__ cw,   const float* __restrict__ ew)
{
    __shared__ __align__(16) float As[2][128][A_KS];
    __shared__ __align__(16) float Bs[2][16][B_KS];
    __shared__ __align__(16) float Bs3[2][16][8];

    const int tid  = threadIdx.x;
    const int lane = tid & 31;
    const int wid  = tid >> 5;
    const int g    = lane >> 2;
    const int t    = lane & 3;
    const int wm   = (wid >> 1) * 64;
    const int wn   = (wid & 1) * 32;
    const int bx   = blockIdx.x;
    const int m0   = blockIdx.y * 128;
    const int n0   = bx * 64;
    const bool do_ba = (bx == 2) && (wn == 0);

    float acc[4][4][4];
#pragma unroll
    for (int i = 0; i < 4; i++)
#pragma unroll
        for (int j = 0; j < 4; j++)
#pragma unroll
            for (int r = 0; r < 4; r++) acc[i][j][r] = 0.f;
    float accB[4][4];
#pragma unroll
    for (int i = 0; i < 4; i++)
#pragma unroll
        for (int r = 0; r < 4; r++) accB[i][r] = 0.f;

    auto load_tiles = [&](int k0, int buf) {
#pragma unroll
        for (int i = 0; i < 4; i++) {
            int e   = i * 128 + tid;
            int row = e >> 2;
            int cq  = (e & 3) * 4;
            CP16(su32(&As[buf][row][cq]),
                 A + (size_t)(m0 + row) * JDIM + k0 + cq);
        }
#pragma unroll
        for (int i = 0; i < 2; i++) {
            int e  = i * 128 + tid;
            int kk = e >> 4;
            int cq = (e & 15) * 4;
            CP16(su32(&Bs[buf][kk][cq]),
                 g_Bpack + (size_t)(k0 + kk) * NPRE + n0 + cq);
        }
        if (bx == 2 && tid < 32) {
            int kk = tid >> 1;
            int cq = (tid & 1) * 4;
            CP16(su32(&Bs3[buf][kk][cq]),
                 g_Bpack3 + (size_t)(k0 + kk) * 8 + cq);
        }
    };

    load_tiles(0, 0);
    CP_COMMIT();

    for (int kt = 0; kt < 16; kt++) {
        const int cur = kt & 1;
        if (kt < 15) {
            load_tiles((kt + 1) * 16, cur ^ 1);
            CP_COMMIT();
            CP_WAIT1();
        } else {
            CP_WAIT0();
        }
        __syncthreads();

#pragma unroll
        for (int ks = 0; ks < 2; ks++) {
            const int kb = ks * 8;
            unsigned a[4][4], b[4][2];
#pragma unroll
            for (int mt = 0; mt < 4; mt++) {
                int r = wm + mt * 16 + g;
                a[mt][0] = futf(As[cur][r][kb + t]);
                a[mt][1] = futf(As[cur][r + 8][kb + t]);
                a[mt][2] = futf(As[cur][r][kb + t + 4]);
                a[mt][3] = futf(As[cur][r + 8][kb + t + 4]);
            }
#pragma unroll
            for (int nt = 0; nt < 4; nt++) {
                int n = wn + nt * 8 + g;
                b[nt][0] = fu(Bs[cur][kb + t][n]);
                b[nt][1] = fu(Bs[cur][kb + t + 4][n]);
            }
#pragma unroll
            for (int mt = 0; mt < 4; mt++)
#pragma unroll
                for (int nt = 0; nt < 4; nt++)
                    MMA_TF32(acc[mt][nt], a[mt], b[nt]);
            if (do_ba) {
                unsigned b3[2];
                b3[0] = fu(Bs3[cur][kb + t][g]);
                b3[1] = fu(Bs3[cur][kb + t + 4][g]);
#pragma unroll
                for (int mt = 0; mt < 4; mt++)
                    MMA_TF32(accB[mt], a[mt], b3);
            }
        }
        __syncthreads();
    }

    if (bx == 2) {
#pragma unroll
        for (int mt = 0; mt < 4; mt++) {
#pragma unroll
            for (int nt = 0; nt < 4; nt++) {
                int row = m0 + wm + mt * 16 + g;
                int col = wn + nt * 8 + 2 * t;
                *(float2*)(g_v + (size_t)row * 64 + col) =
                    make_float2(acc[mt][nt][0], acc[mt][nt][1]);
                *(float2*)(g_v + (size_t)(row + 8) * 64 + col) =
                    make_float2(acc[mt][nt][2], acc[mt][nt][3]);
            }
        }
        if (do_ba) {
            const int bidx = m0 >> 15;
            const float Kv = fminf(fabsf(curv[bidx]), 10.f);
            const float Sv = fminf(fmaxf(ent[bidx], 0.f), 5.f);
            const int c0 = 2 * t, c1 = 2 * t + 1;
            const bool isA = (t >= 2);
            const int h0 = isA ? c0 - 4 : c0;
            const int h1 = isA ? c1 - 4 : c1;
            const float off0 = isA ? Wab[h0] : Wbb[h0];
            const float off1 = isA ? Wab[h1] : Wbb[h1];
            const float mod0 = isA ? Sv * ew[h0] : Kv * cw[h0];
            const float mod1 = isA ? Sv * ew[h1] : Kv * cw[h1];
            float* dstba = isA ? g_alpha : g_beta;
#pragma unroll
            for (int mt = 0; mt < 4; mt++) {
#pragma unroll
                for (int half = 0; half < 2; half++) {
                    int row = m0 + wm + mt * 16 + g + half * 8;
                    float p0 = accB[mt][half * 2 + 0];
                    float p1 = accB[mt][half * 2 + 1];
                    dstba[(size_t)row * HEADS + h0] = sigm(sigm(p0 + off0) + mod0);
                    dstba[(size_t)row * HEADS + h1] = sigm(sigm(p1 + off1) + mod1);
                }
            }
        }
        return;
    }

    const float* wp = (bx == 0) ? lqw : lkw;
    const float* bp = (bx == 0) ? lqb : lkb;
    float wv0 = wp[2 * t], wv1 = wp[2 * t + 1];
    float wv2 = wp[8 + 2 * t], wv3 = wp[8 + 2 * t + 1];
    float bb0 = bp[2 * t], bb1 = bp[2 * t + 1];
    float bb2 = bp[8 + 2 * t], bb3 = bp[8 + 2 * t + 1];
    float* dst = (bx == 0) ? g_q : g_k;
    const float inv16 = 1.f / 16.f;

#pragma unroll
    for (int mt = 0; mt < 4; mt++) {
#pragma unroll
        for (int hl = 0; hl < 2; hl++) {
            const int nt0 = 2 * hl, nt1 = 2 * hl + 1;
#pragma unroll
            for (int half = 0; half < 2; half++) {
                const int c0 = half * 2, c1 = half * 2 + 1;
                float x0 = acc[mt][nt0][c0], x1 = acc[mt][nt0][c1];
                float x2 = acc[mt][nt1][c0], x3 = acc[mt][nt1][c1];
                float mu = qred(x0 + x1 + x2 + x3) * inv16;
                float d0 = x0 - mu, d1 = x1 - mu, d2 = x2 - mu, d3 = x3 - mu;
                float var = qred(d0*d0 + d1*d1 + d2*d2 + d3*d3) * inv16;
                float rs = 1.f / sqrtf(var + 1e-5f);
                float n0v = d0 * rs * wv0 + bb0;
                float n1v = d1 * rs * wv1 + bb1;
                float n2v = d2 * rs * wv2 + bb2;
                float n3v = d3 * rs * wv3 + bb3;
                if (bx == 1) {
                    float ss = qred(n0v*n0v + n1v*n1v + n2v*n2v + n3v*n3v);
                    float sc = 1.f / fmaxf(sqrtf(ss), 1e-12f);
                    n0v *= sc; n1v *= sc; n2v *= sc; n3v *= sc;
                }
                int row = m0 + wm + mt * 16 + g + half * 8;
                int cb  = wn + hl * 16 + 2 * t;
                *(float2*)(dst + (size_t)row * 64 + cb)     = make_float2(n0v, n1v);
                *(float2*)(dst + (size_t)row * 64 + cb + 8) = make_float2(n2v, n3v);
            }
        }
    }
}

// ---------------------------------------------------------------------------
// Scan pass 1 (CCH=32): 32-thread blocks, thread (h,i2) owns rows i2, i2+8.
// ---------------------------------------------------------------------------
__global__ __launch_bounds__(32) void scan_phase1()
{
    const int n   = blockIdx.x;
    const int c   = blockIdx.y;
    const int tid = threadIdx.x;
    const int h   = tid >> 3;
    const int i2  = tid & 7;
    const int r0  = i2;
    const int r1  = i2 + 8;

    __shared__ __align__(16) float ks[CCH * 64];
    __shared__ __align__(16) float vs[CCH * 64];
    __shared__ float bs[CCH * HEADS];
    __shared__ float as_[CCH * HEADS];

    u64 Ta[8], Tb[8], Ua[8], Ub[8];
#pragma unroll
    for (int p = 0; p < 8; p++) {
        Ta[p] = pk2((2*p == r0) ? 1.f : 0.f, (2*p+1 == r0) ? 1.f : 0.f);
        Tb[p] = pk2((2*p == r1) ? 1.f : 0.f, (2*p+1 == r1) ? 1.f : 0.f);
        Ua[p] = 0ull; Ub[p] = 0ull;
    }

    const size_t base  = ((size_t)n * TLEN + (size_t)c * CCH) * 64;
    const size_t base2 = ((size_t)n * TLEN + (size_t)c * CCH) * HEADS;
    {
        const float4* gk4 = (const float4*)(g_k + base);
        const float4* gv4 = (const float4*)(g_v + base);
#pragma unroll
        for (int idx = tid; idx < CCH * 16; idx += 32) {
            ((float4*)ks)[idx] = gk4[idx];
            ((float4*)vs)[idx] = gv4[idx];
        }
#pragma unroll
        for (int idx = tid; idx < CCH * HEADS; idx += 32) {
            bs[idx]  = g_beta[base2 + idx];
            as_[idx] = g_alpha[base2 + idx];
        }
    }
    __syncthreads();

    for (int tt = 0; tt < CCH; tt++) {
        const u64* kp2 = (const u64*)(ks + tt * 64 + h * 16);
        u64 k2[8];
#pragma unroll
        for (int p = 0; p < 8; p++) k2[p] = kp2[p];

        float Tka = pdot8(Ta, k2);
        float Tkb = pdot8(Tb, k2);
        float Uka = pdot8(Ua, k2);
        float Ukb = pdot8(Ub, k2);

        float a  = as_[tt * HEADS + h];
        float b  = bs [tt * HEADS + h];
        float va = vs [tt * 64 + h * 16 + r0];
        float vb = vs [tt * 64 + h * 16 + r1];
        float cTa = -a * Tka, cTb = -a * Tkb;
        float cUa = b * va - a * Uka;
        float cUb = b * vb - a * Ukb;
        u64 cTa2 = pk2(cTa, cTa), cTb2 = pk2(cTb, cTb);
        u64 cUa2 = pk2(cUa, cUa), cUb2 = pk2(cUb, cUb);

#pragma unroll
        for (int p = 0; p < 8; p++) {
            Ta[p] = ffma2(k2[p], cTa2, Ta[p]);
            Tb[p] = ffma2(k2[p], cTb2, Tb[p]);
            Ua[p] = ffma2(k2[p], cUa2, Ua[p]);
            Ub[p] = ffma2(k2[p], cUb2, Ub[p]);
        }
    }

    const size_t ob = ((size_t)(n * NCHUNK + c) * HEADS + h) * 256;
    u64* Td0 = (u64*)(g_T + ob + r0 * 16);
    u64* Td1 = (u64*)(g_T + ob + r1 * 16);
    u64* Ud0 = (u64*)(g_U + ob + r0 * 16);
    u64* Ud1 = (u64*)(g_U + ob + r1 * 16);
#pragma unroll
    for (int p = 0; p < 8; p++) {
        Td0[p] = Ta[p]; Td1[p] = Tb[p];
        Ud0[p] = Ua[p]; Ud1[p] = Ub[p];
    }
}

// ---------------------------------------------------------------------------
// Scan pass 2a: per (n, group of 8 chunks): local prefix operators.
// Overwrites g_T/g_U in place with the PRE-chunk prefix (T~, U~); stores
// group totals to g_GT/g_GU. 64 threads = (h, i).
// ---------------------------------------------------------------------------
__global__ __launch_bounds__(64) void scan_phase2a()
{
    const int n   = blockIdx.x;
    const int grp = blockIdx.y;
    const int tid = threadIdx.x;
    const int h   = tid >> 4;
    const int i   = tid & 15;

    __shared__ __align__(16) float Tj[HEADS * 256];
    __shared__ __align__(16) float Uj[HEADS * 256];

    float Tr[16], Ur[16];
#pragma unroll
    for (int j = 0; j < 16; j++) { Tr[j] = (j == i) ? 1.f : 0.f; Ur[j] = 0.f; }

    for (int j = 0; j < GCH; j++) {
        const int c = grp * GCH + j;
        const size_t ob = (size_t)(n * NCHUNK + c) * HEADS * 256;
        // stage chunk op j
        {
            const float4* Tg = (const float4*)(g_T + ob);
            const float4* Ug = (const float4*)(g_U + ob);
#pragma unroll
            for (int e = 0; e < 4; e++) {
                ((float4*)Tj)[tid + e * 64] = Tg[tid + e * 64];
                ((float4*)Uj)[tid + e * 64] = Ug[tid + e * 64];
            }
        }
        __syncthreads();
        // overwrite with pre-chunk prefix
        {
            float* Td = g_T + ob + (size_t)h * 256 + i * 16;
            float* Ud = g_U + ob + (size_t)h * 256 + i * 16;
#pragma unroll
            for (int e = 0; e < 4; e++) {
                *(float4*)(Td + 4*e) = make_float4(Tr[4*e], Tr[4*e+1], Tr[4*e+2], Tr[4*e+3]);
                *(float4*)(Ud + 4*e) = make_float4(Ur[4*e], Ur[4*e+1], Ur[4*e+2], Ur[4*e+3]);
            }
        }
        // compose: T~ = T~ * Tj ; U~ = U~ * Tj + Uj
        u64 Tn2[8], Un2[8];
        const u64* Ujh = (const u64*)(Uj + h * 256 + i * 16);
#pragma unroll
        for (int p = 0; p < 8; p++) { Un2[p] = Ujh[p]; Tn2[p] = 0ull; }
        const float* Tjh = Tj + h * 256;
#pragma unroll
        for (int u = 0; u < 16; u++) {
            u64 tu2 = pk2(Tr[u], Tr[u]);
            u64 uu2 = pk2(Ur[u], Ur[u]);
            const u64* Tju = (const u64*)(Tjh + u * 16);
#pragma unroll
            for (int p = 0; p < 8; p++) {
                Tn2[p] = ffma2(tu2, Tju[p], Tn2[p]);
                Un2[p] = ffma2(uu2, Tju[p], Un2[p]);
            }
        }
#pragma unroll
        for (int p = 0; p < 8; p++) {
            upk2(Tn2[p], Tr[2*p], Tr[2*p+1]);
            upk2(Un2[p], Ur[2*p], Ur[2*p+1]);
        }
        __syncthreads();
    }

    // group totals
    {
        const size_t og = (size_t)(n * NGRP + grp) * HEADS * 256 + (size_t)h * 256 + i * 16;
#pragma unroll
        for (int e = 0; e < 4; e++) {
            *(float4*)(g_GT + og + 4*e) = make_float4(Tr[4*e], Tr[4*e+1], Tr[4*e+2], Tr[4*e+3]);
            *(float4*)(g_GU + og + 4*e) = make_float4(Ur[4*e], Ur[4*e+1], Ur[4*e+2], Ur[4*e+3]);
        }
    }
}

// ---------------------------------------------------------------------------
// Scan pass 2b: serial over 8 group totals per n -> group start states g_G.
// ---------------------------------------------------------------------------
__global__ __launch_bounds__(64) void scan_phase2b()
{
    const int n   = blockIdx.x;
    const int tid = threadIdx.x;
    const int h   = tid >> 4;
    const int i   = tid & 15;

    __shared__ __align__(16) float Ts[HEADS * 256];
    __shared__ __align__(16) float Us[HEADS * 256];

    float Gr[16];
#pragma unroll
    for (int j = 0; j < 16; j++) Gr[j] = 0.f;

    for (int grp = 0; grp < NGRP; grp++) {
        const size_t og = (size_t)(n * NGRP + grp) * HEADS * 256;
        {
            const float4* Tg = (const float4*)(g_GT + og);
            const float4* Ug = (const float4*)(g_GU + og);
#pragma unroll
            for (int e = 0; e < 4; e++) {
                ((float4*)Ts)[tid + e * 64] = Tg[tid + e * 64];
                ((float4*)Us)[tid + e * 64] = Ug[tid + e * 64];
            }
        }
        // store group start state
        {
            float* Gd = g_G + og + (size_t)h * 256 + i * 16;
#pragma unroll
            for (int e = 0; e < 4; e++)
                *(float4*)(Gd + 4*e) = make_float4(Gr[4*e], Gr[4*e+1], Gr[4*e+2], Gr[4*e+3]);
        }
        __syncthreads();

        u64 Gn2[8];
        const u64* Uh = (const u64*)(Us + h * 256 + i * 16);
#pragma unroll
        for (int p = 0; p < 8; p++) Gn2[p] = Uh[p];
        const float* Th = Ts + h * 256;
#pragma unroll
        for (int u = 0; u < 16; u++) {
            u64 gu2 = pk2(Gr[u], Gr[u]);
            const u64* Tu = (const u64*)(Th + u * 16);
#pragma unroll
            for (int p = 0; p < 8; p++) Gn2[p] = ffma2(gu2, Tu[p], Gn2[p]);
        }
#pragma unroll
        for (int p = 0; p < 8; p++) upk2(Gn2[p], Gr[2*p], Gr[2*p+1]);
        __syncthreads();
    }
}

// ---------------------------------------------------------------------------
// Scan pass 3: reconstruct S_c = G_g * T~_c + U~_c, then replay chunk.
// 32-thread blocks, 2 rows/thread. Prefix-T staged through ks buffer.
// ---------------------------------------------------------------------------
__global__ __launch_bounds__(32) void scan_phase3()
{
    const int n   = blockIdx.x;
    const int c   = blockIdx.y;
    const int tid = threadIdx.x;
    const int h   = tid >> 3;
    const int i2  = tid & 7;
    const int r0  = i2;
    const int r1  = i2 + 8;

    __shared__ __align__(16) float ks[16 * 64];   // doubles as Tp staging
    __shared__ __align__(16) float qs[16 * 64];
    __shared__ __align__(16) float vs[16 * 64];
    __shared__ float bs[16 * HEADS];
    __shared__ float as_[16 * HEADS];

    // ---- reconstruct M = G * T~ + U~ ----
    u64 Ma[8], Mb[8];
    {
        const size_t obc = (size_t)(n * NCHUNK + c) * HEADS * 256;
        // stage prefix T~ (all 4 heads) into ks
        {
            const float4* Tg = (const float4*)(g_T + obc);
#pragma unroll
            for (int e = 0; e < 8; e++)
                ((float4*)ks)[tid + e * 32] = Tg[tid + e * 32];
        }
        __syncthreads();

        const int grp = c >> 3;   // c / GCH
        const size_t og = (size_t)(n * NGRP + grp) * HEADS * 256 + (size_t)h * 256;
        const float* Gr0 = g_G + og + r0 * 16;
        const float* Gr1 = g_G + og + r1 * 16;
        const u64* Up0 = (const u64*)(g_U + obc + (size_t)h * 256 + r0 * 16);
        const u64* Up1 = (const u64*)(g_U + obc + (size_t)h * 256 + r1 * 16);
#pragma unroll
        for (int p = 0; p < 8; p++) { Ma[p] = Up0[p]; Mb[p] = Up1[p]; }
        const float* Tph = ks + h * 256;
#pragma unroll
        for (int u = 0; u < 16; u++) {
            float ga = Gr0[u], gb = Gr1[u];
            u64 ga2 = pk2(ga, ga), gb2 = pk2(gb, gb);
            const u64* Tpu = (const u64*)(Tph + u * 16);
#pragma unroll
            for (int p = 0; p < 8; p++) {
                Ma[p] = ffma2(ga2, Tpu[p], Ma[p]);
                Mb[p] = ffma2(gb2, Tpu[p], Mb[p]);
            }
        }
        __syncthreads();   // done with ks-as-Tp before k staging below
    }

    for (int qt = 0; qt < 2; qt++) {
        const size_t base  = ((size_t)n * TLEN + (size_t)c * CCH + qt * 16) * 64;
        const size_t base2 = ((size_t)n * TLEN + (size_t)c * CCH + qt * 16) * HEADS;
        {
            const float4* gk4 = (const float4*)(g_k + base);
            const float4* gq4 = (const float4*)(g_q + base);
            const float4* gv4 = (const float4*)(g_v + base);
#pragma unroll
            for (int idx = tid; idx < 16 * 16; idx += 32) {
                ((float4*)ks)[idx] = gk4[idx];
                ((float4*)qs)[idx] = gq4[idx];
                ((float4*)vs)[idx] = gv4[idx];
            }
#pragma unroll
            for (int idx = tid; idx < 16 * HEADS; idx += 32) {
                bs[idx]  = g_beta[base2 + idx];
                as_[idx] = g_alpha[base2 + idx];
            }
        }
        __syncthreads();

        for (int tt = 0; tt < 16; tt++) {
            const u64* kp2 = (const u64*)(ks + tt * 64 + h * 16);
            u64 k2[8];
#pragma unroll
            for (int p = 0; p < 8; p++) k2[p] = kp2[p];

            float Mka = pdot8(Ma, k2);
            float Mkb = pdot8(Mb, k2);

            float a  = as_[tt * HEADS + h];
            float b  = bs [tt * HEADS + h];
            float va = vs [tt * 64 + h * 16 + r0];
            float vb = vs [tt * 64 + h * 16 + r1];
            float ca = b * va - a * Mka;
            float cb = b * vb - a * Mkb;
            u64 ca2 = pk2(ca, ca), cb2 = pk2(cb, cb);

#pragma unroll
            for (int p = 0; p < 8; p++) {
                Ma[p] = ffma2(k2[p], ca2, Ma[p]);
                Mb[p] = ffma2(k2[p], cb2, Mb[p]);
            }

            const u64* qp2 = (const u64*)(qs + tt * 64 + h * 16);
            u64 q2[8];
#pragma unroll
            for (int p = 0; p < 8; p++) q2[p] = qp2[p];
            float oa  = pdot8(Ma, q2);
            float ob_ = pdot8(Mb, q2);

            g_o[base + tt * 64 + h * 16 + r0] = oa;
            g_o[base + tt * 64 + h * 16 + r1] = ob_;
        }
        __syncthreads();
    }
}

// ---------------------------------------------------------------------------
// Kernel D (tf32, cp.async 2-stage, BK=16): fib = o @ out_w^T + out_b,
// scatter to (B,T,P,K).
// ---------------------------------------------------------------------------
__global__ __launch_bounds__(128) void gemmD_kernel(const float* __restrict__ ob,
                                                    float* __restrict__ out)
{
    __shared__ __align__(16) float As[2][128][A_KS];
    __shared__ __align__(16) float Bs[2][16][B_KS];

    const int tid  = threadIdx.x;
    const int lane = tid & 31;
    const int wid  = tid >> 5;
    const int g    = lane >> 2;
    const int t    = lane & 3;
    const int wm   = (wid >> 1) * 64;
    const int wn   = (wid & 1) * 32;
    const int m0   = blockIdx.y * 128;
    const int n0   = blockIdx.x * 64;

    float acc[4][4][4];
#pragma unroll
    for (int i = 0; i < 4; i++)
#pragma unroll
        for (int j = 0; j < 4; j++)
#pragma unroll
            for (int r = 0; r < 4; r++) acc[i][j][r] = 0.f;

    auto load_tiles = [&](int k0, int buf) {
#pragma unroll
        for (int i = 0; i < 4; i++) {
            int e   = i * 128 + tid;
            int row = e >> 2;
            int cq  = (e & 3) * 4;
            CP16(su32(&As[buf][row][cq]),
                 g_o + (size_t)(m0 + row) * 64 + k0 + cq);
        }
#pragma unroll
        for (int i = 0; i < 2; i++) {
            int e  = i * 128 + tid;
            int kk = e >> 4;
            int cq = (e & 15) * 4;
            CP16(su32(&Bs[buf][kk][cq]),
                 g_Bpack2 + (size_t)(k0 + kk) * KOUT + n0 + cq);
        }
    };

    load_tiles(0, 0);
    CP_COMMIT();

    for (int kt = 0; kt < 4; kt++) {
        const int cur = kt & 1;
        if (kt < 3) {
            load_tiles((kt + 1) * 16, cur ^ 1);
            CP_COMMIT();
            CP_WAIT1();
        } else {
            CP_WAIT0();
        }
        __syncthreads();

#pragma unroll
        for (int ks = 0; ks < 2; ks++) {
            const int kb = ks * 8;
            unsigned a[4][4], b[4][2];
#pragma unroll
            for (int mt = 0; mt < 4; mt++) {
                int r = wm + mt * 16 + g;
                a[mt][0] = futf(As[cur][r][kb + t]);
                a[mt][1] = futf(As[cur][r + 8][kb + t]);
                a[mt][2] = futf(As[cur][r][kb + t + 4]);
                a[mt][3] = futf(As[cur][r + 8][kb + t + 4]);
            }
#pragma unroll
            for (int nt = 0; nt < 4; nt++) {
                int n = wn + nt * 8 + g;
                b[nt][0] = fu(Bs[cur][kb + t][n]);
                b[nt][1] = fu(Bs[cur][kb + t + 4][n]);
            }
#pragma unroll
            for (int mt = 0; mt < 4; mt++)
#pragma unroll
                for (int nt = 0; nt < 4; nt++)
                    MMA_TF32(acc[mt][nt], a[mt], b[nt]);
        }
        __syncthreads();
    }

    const int nseq = m0 >> 11;
    const int tb   = m0 & 2047;
    const int bb   = nseq >> 4;
    const int pp   = nseq & 15;
#pragma unroll
    for (int mt = 0; mt < 4; mt++) {
#pragma unroll
        for (int nt = 0; nt < 4; nt++) {
            int r   = wm + mt * 16 + g;
            int col = n0 + wn + nt * 8 + 2 * t;
            float b0 = ob[col], b1 = ob[col + 1];
            int t1 = tb + r;
            size_t d1 = (((size_t)bb * TLEN + t1) * 16 + pp) * KOUT + col;
            *(float2*)(out + d1) = make_float2(acc[mt][nt][0] + b0,
                                               acc[mt][nt][1] + b1);
            int t2 = t1 + 8;
            size_t d2 = (((size_t)bb * TLEN + t2) * 16 + pp) * KOUT + col;
            *(float2*)(out + d2) = make_float2(acc[mt][nt][2] + b0,
                                               acc[mt][nt][3] + b1);
        }
    }
}

// ---------------------------------------------------------------------------
// launch
// ---------------------------------------------------------------------------
extern "C" void kernel_launch(void* const* d_in, const int* in_sizes, int n_in,
                              void* d_out, int out_size)
{
    const float* joint = (const float*)d_in[0];
    const float* curv  = (const float*)d_in[1];
    const float* ent   = (const float*)d_in[2];
    const float* Wq    = (const float*)d_in[3];
    const float* Wk    = (const float*)d_in[4];
    const float* Wv    = (const float*)d_in[5];
    const float* Wbw   = (const float*)d_in[6];
    const float* Wbb   = (const float*)d_in[7];
    const float* Waw   = (const float*)d_in[8];
    const float* Wab   = (const float*)d_in[9];
    const float* cw    = (const float*)d_in[10];
    const float* ew    = (const float*)d_in[11];
    const float* out_w = (const float*)d_in[12];
    const float* out_b = (const float*)d_in[13];
    const float* lqw   = (const float*)d_in[14];
    const float* lqb   = (const float*)d_in[15];
    const float* lkw   = (const float*)d_in[16];
    const float* lkb   = (const float*)d_in[17];
    float* out = (float*)d_out;

    pack_kernel<<<256, 256>>>(Wq, Wk, Wv, out_w, Wbw, Waw);

    gemmA_kernel<<<dim3(3, M_TOK / 128), 128>>>(joint, lqw, lqb, lkw, lkb,
                                                curv, ent, Wbb, Wab, cw, ew);

    scan_phase1<<<dim3(NSEQ, NCHUNK), 32>>>();
    scan_phase2a<<<dim3(NSEQ, NGRP), 64>>>();
    scan_phase2b<<<NSEQ, 64>>>();
    scan_phase3<<<dim3(NSEQ, NCHUNK), 32>>>();

    gemmD_kernel<<<dim3(KOUT / 64, M_TOK / 128), 128>>>(out_b, out);
}

// round 14
// speedup vs baseline: 1.7187x; 1.1655x over previous
#include <cuda_runtime.h>
#include <cuda_bf16.h>
#include <math.h>

// ---------------------------------------------------------------------------
// B=4, T=2048, P=16, J=256, H=4, D=16, MEM=64, K_OUT=192
// N = 64 sequences; tokens M_TOK = 131072
// gemmA (tf32, cp.async): q->LN->g_q, k->LN+L2->g_k, v->g_v, beta/alpha fused.
// Scan (group-direct): phaseG builds 8 group operators per seq by 256-step
// walks; phase2b composes them; phase3g replays each group from its start
// state. gemmD (tf32, cp.async) + scatter.
// ---------------------------------------------------------------------------

#define M_TOK   131072
#define JDIM    256
#define NPRE    192
#define NSEQ    64
#define TLEN    2048
#define HEADS   4
#define KOUT    192
#define NGRP    8
#define GTOK    (TLEN / NGRP)   // 256 tokens per group

typedef unsigned long long u64;

// -------- scratch (device globals; no allocation allowed) --------
__device__ float g_Bpack [(size_t)JDIM * NPRE];
__device__ float g_Bpack2[(size_t)64 * KOUT];
__device__ float g_Bpack3[(size_t)JDIM * 8];
__device__ float g_q     [(size_t)M_TOK * 64];
__device__ float g_k     [(size_t)M_TOK * 64];
__device__ float g_v     [(size_t)M_TOK * 64];
__device__ float g_beta  [(size_t)M_TOK * HEADS];
__device__ float g_alpha [(size_t)M_TOK * HEADS];
__device__ float g_o     [(size_t)M_TOK * 64];
__device__ float g_GT[(size_t)NSEQ * NGRP * HEADS * 256];   // group operators
__device__ float g_GU[(size_t)NSEQ * NGRP * HEADS * 256];
__device__ float g_G [(size_t)NSEQ * NGRP * HEADS * 256];   // group start states

// ---- helpers ----
__device__ __forceinline__ float tf32r(float x)
{
    unsigned u;
    asm("cvt.rna.tf32.f32 %0, %1;" : "=r"(u) : "f"(x));
    return __uint_as_float(u);
}
__device__ __forceinline__ unsigned fu(float x) { return __float_as_uint(x); }
__device__ __forceinline__ unsigned futf(float x)
{
    unsigned u;
    asm("cvt.rna.tf32.f32 %0, %1;" : "=r"(u) : "f"(x));
    return u;
}

__device__ __forceinline__ u64 pk2(float lo, float hi)
{
    u64 r;
    asm("mov.b64 %0, {%1, %2};" : "=l"(r) : "f"(lo), "f"(hi));
    return r;
}
__device__ __forceinline__ void upk2(u64 v, float& lo, float& hi)
{
    asm("mov.b64 {%0, %1}, %2;" : "=f"(lo), "=f"(hi) : "l"(v));
}
__device__ __forceinline__ u64 ffma2(u64 a, u64 b, u64 c)
{
    u64 d;
    asm("fma.rn.f32x2 %0, %1, %2, %3;" : "=l"(d) : "l"(a), "l"(b), "l"(c));
    return d;
}
__device__ __forceinline__ float pdot8(const u64* r, const u64* k)
{
    u64 a0 = 0ull, a1 = 0ull;
#pragma unroll
    for (int p = 0; p < 4; p++) {
        a0 = ffma2(r[p],     k[p],     a0);
        a1 = ffma2(r[p + 4], k[p + 4], a1);
    }
    float x0, x1, y0, y1;
    upk2(a0, x0, x1); upk2(a1, y0, y1);
    return (x0 + x1) + (y0 + y1);
}

__device__ __forceinline__ unsigned su32(const void* p)
{
    return (unsigned)__cvta_generic_to_shared(p);
}
#define CP16(dst, src) \
    asm volatile("cp.async.cg.shared.global [%0], [%1], 16;" :: "r"(dst), "l"(src))
#define CP_COMMIT() asm volatile("cp.async.commit_group;")
#define CP_WAIT1()  asm volatile("cp.async.wait_group 1;")
#define CP_WAIT0()  asm volatile("cp.async.wait_group 0;")

#define MMA_TF32(c, a, b)                                                     \
    asm volatile("mma.sync.aligned.m16n8k8.row.col.f32.tf32.tf32.f32 "        \
                 "{%0,%1,%2,%3}, {%4,%5,%6,%7}, {%8,%9}, {%0,%1,%2,%3};"      \
                 : "+f"((c)[0]), "+f"((c)[1]), "+f"((c)[2]), "+f"((c)[3])     \
                 : "r"((a)[0]), "r"((a)[1]), "r"((a)[2]), "r"((a)[3]),        \
                   "r"((b)[0]), "r"((b)[1]))

__device__ __forceinline__ float qred(float x)
{
    x += __shfl_xor_sync(0xffffffffu, x, 1);
    x += __shfl_xor_sync(0xffffffffu, x, 2);
    return x;
}
__device__ __forceinline__ float sigm(float x) { return 1.f / (1.f + expf(-x)); }

// ---------------------------------------------------------------------------
// Kernel 0: pack weights (k-major) + round to tf32
// ---------------------------------------------------------------------------
__global__ void pack_kernel(const float* __restrict__ Wq,
                            const float* __restrict__ Wk,
                            const float* __restrict__ Wv,
                            const float* __restrict__ out_w,
                            const float* __restrict__ Wbw,
                            const float* __restrict__ Waw)
{
    int idx = blockIdx.x * blockDim.x + threadIdx.x;
    if (idx < JDIM * NPRE) {
        int k = idx / NPRE;
        int o = idx - k * NPRE;
        float val;
        if      (o < 64)  val = Wq[(size_t)o       * JDIM + k];
        else if (o < 128) val = Wk[(size_t)(o-64)  * JDIM + k];
        else              val = Wv[(size_t)(o-128) * JDIM + k];
        g_Bpack[idx] = tf32r(val);
    }
    int idx2 = idx - JDIM * NPRE;
    if (idx2 >= 0 && idx2 < 64 * KOUT) {
        int k = idx2 / KOUT;
        int o = idx2 - k * KOUT;
        g_Bpack2[idx2] = tf32r(out_w[(size_t)o * 64 + k]);
    }
    int idx3 = idx2 - 64 * KOUT;
    if (idx3 >= 0 && idx3 < JDIM * 8) {
        int k = idx3 >> 3;
        int o = idx3 & 7;
        float val = (o < 4) ? Wbw[(size_t)o * JDIM + k]
                            : Waw[(size_t)(o - 4) * JDIM + k];
        g_Bpack3[idx3] = tf32r(val);
    }
}

// ---------------------------------------------------------------------------
// Kernel A: tf32 GEMM, BM=128 BN=64 BK=16, cp.async 2-stage, 128 threads.
// bx=0: q -> LN -> g_q ; bx=1: k -> LN+L2 -> g_k ;
// bx=2: v -> g_v + fused beta/alpha.
// ---------------------------------------------------------------------------
#define A_KS  20
#define B_KS  68

__global__ __launch_bounds__(128) void gemmA_kernel(
    const float* __restrict__ A,
    const float* __restrict__ lqw, const float* __restrict__ lqb,
    const float* __restrict__ lkw, const float* __restrict__ lkb,
    const float* __restrict__ curv, const float* __restrict__ ent,
    const float* __restrict__ Wbb,  const float* __restrict__ Wab,
    const float* __restrict__ cw,   const float* __restrict__ ew)
{
    __shared__ __align__(16) float As[2][128][A_KS];
    __shared__ __align__(16) float Bs[2][16][B_KS];
    __shared__ __align__(16) float Bs3[2][16][8];

    const int tid  = threadIdx.x;
    const int lane = tid & 31;
    const int wid  = tid >> 5;
    const int g    = lane >> 2;
    const int t    = lane & 3;
    const int wm   = (wid >> 1) * 64;
    const int wn   = (wid & 1) * 32;
    const int bx   = blockIdx.x;
    const int m0   = blockIdx.y * 128;
    const int n0   = bx * 64;
    const bool do_ba = (bx == 2) && (wn == 0);

    float acc[4][4][4];
#pragma unroll
    for (int i = 0; i < 4; i++)
#pragma unroll
        for (int j = 0; j < 4; j++)
#pragma unroll
            for (int r = 0; r < 4; r++) acc[i][j][r] = 0.f;
    float accB[4][4];
#pragma unroll
    for (int i = 0; i < 4; i++)
#pragma unroll
        for (int r = 0; r < 4; r++) accB[i][r] = 0.f;

    auto load_tiles = [&](int k0, int buf) {
#pragma unroll
        for (int i = 0; i < 4; i++) {
            int e   = i * 128 + tid;
            int row = e >> 2;
            int cq  = (e & 3) * 4;
            CP16(su32(&As[buf][row][cq]),
                 A + (size_t)(m0 + row) * JDIM + k0 + cq);
        }
#pragma unroll
        for (int i = 0; i < 2; i++) {
            int e  = i * 128 + tid;
            int kk = e >> 4;
            int cq = (e & 15) * 4;
            CP16(su32(&Bs[buf][kk][cq]),
                 g_Bpack + (size_t)(k0 + kk) * NPRE + n0 + cq);
        }
        if (bx == 2 && tid < 32) {
            int kk = tid >> 1;
            int cq = (tid & 1) * 4;
            CP16(su32(&Bs3[buf][kk][cq]),
                 g_Bpack3 + (size_t)(k0 + kk) * 8 + cq);
        }
    };

    load_tiles(0, 0);
    CP_COMMIT();

    for (int kt = 0; kt < 16; kt++) {
        const int cur = kt & 1;
        if (kt < 15) {
            load_tiles((kt + 1) * 16, cur ^ 1);
            CP_COMMIT();
            CP_WAIT1();
        } else {
            CP_WAIT0();
        }
        __syncthreads();

#pragma unroll
        for (int ks = 0; ks < 2; ks++) {
            const int kb = ks * 8;
            unsigned a[4][4], b[4][2];
#pragma unroll
            for (int mt = 0; mt < 4; mt++) {
                int r = wm + mt * 16 + g;
                a[mt][0] = futf(As[cur][r][kb + t]);
                a[mt][1] = futf(As[cur][r + 8][kb + t]);
                a[mt][2] = futf(As[cur][r][kb + t + 4]);
                a[mt][3] = futf(As[cur][r + 8][kb + t + 4]);
            }
#pragma unroll
            for (int nt = 0; nt < 4; nt++) {
                int n = wn + nt * 8 + g;
                b[nt][0] = fu(Bs[cur][kb + t][n]);
                b[nt][1] = fu(Bs[cur][kb + t + 4][n]);
            }
#pragma unroll
            for (int mt = 0; mt < 4; mt++)
#pragma unroll
                for (int nt = 0; nt < 4; nt++)
                    MMA_TF32(acc[mt][nt], a[mt], b[nt]);
            if (do_ba) {
                unsigned b3[2];
                b3[0] = fu(Bs3[cur][kb + t][g]);
                b3[1] = fu(Bs3[cur][kb + t + 4][g]);
#pragma unroll
                for (int mt = 0; mt < 4; mt++)
                    MMA_TF32(accB[mt], a[mt], b3);
            }
        }
        __syncthreads();
    }

    if (bx == 2) {
#pragma unroll
        for (int mt = 0; mt < 4; mt++) {
#pragma unroll
            for (int nt = 0; nt < 4; nt++) {
                int row = m0 + wm + mt * 16 + g;
                int col = wn + nt * 8 + 2 * t;
                *(float2*)(g_v + (size_t)row * 64 + col) =
                    make_float2(acc[mt][nt][0], acc[mt][nt][1]);
                *(float2*)(g_v + (size_t)(row + 8) * 64 + col) =
                    make_float2(acc[mt][nt][2], acc[mt][nt][3]);
            }
        }
        if (do_ba) {
            const int bidx = m0 >> 15;
            const float Kv = fminf(fabsf(curv[bidx]), 10.f);
            const float Sv = fminf(fmaxf(ent[bidx], 0.f), 5.f);
            const int c0 = 2 * t, c1 = 2 * t + 1;
            const bool isA = (t >= 2);
            const int h0 = isA ? c0 - 4 : c0;
            const int h1 = isA ? c1 - 4 : c1;
            const float off0 = isA ? Wab[h0] : Wbb[h0];
            const float off1 = isA ? Wab[h1] : Wbb[h1];
            const float mod0 = isA ? Sv * ew[h0] : Kv * cw[h0];
            const float mod1 = isA ? Sv * ew[h1] : Kv * cw[h1];
            float* dstba = isA ? g_alpha : g_beta;
#pragma unroll
            for (int mt = 0; mt < 4; mt++) {
#pragma unroll
                for (int half = 0; half < 2; half++) {
                    int row = m0 + wm + mt * 16 + g + half * 8;
                    float p0 = accB[mt][half * 2 + 0];
                    float p1 = accB[mt][half * 2 + 1];
                    dstba[(size_t)row * HEADS + h0] = sigm(sigm(p0 + off0) + mod0);
                    dstba[(size_t)row * HEADS + h1] = sigm(sigm(p1 + off1) + mod1);
                }
            }
        }
        return;
    }

    const float* wp = (bx == 0) ? lqw : lkw;
    const float* bp = (bx == 0) ? lqb : lkb;
    float wv0 = wp[2 * t], wv1 = wp[2 * t + 1];
    float wv2 = wp[8 + 2 * t], wv3 = wp[8 + 2 * t + 1];
    float bb0 = bp[2 * t], bb1 = bp[2 * t + 1];
    float bb2 = bp[8 + 2 * t], bb3 = bp[8 + 2 * t + 1];
    float* dst = (bx == 0) ? g_q : g_k;
    const float inv16 = 1.f / 16.f;

#pragma unroll
    for (int mt = 0; mt < 4; mt++) {
#pragma unroll
        for (int hl = 0; hl < 2; hl++) {
            const int nt0 = 2 * hl, nt1 = 2 * hl + 1;
#pragma unroll
            for (int half = 0; half < 2; half++) {
                const int c0 = half * 2, c1 = half * 2 + 1;
                float x0 = acc[mt][nt0][c0], x1 = acc[mt][nt0][c1];
                float x2 = acc[mt][nt1][c0], x3 = acc[mt][nt1][c1];
                float mu = qred(x0 + x1 + x2 + x3) * inv16;
                float d0 = x0 - mu, d1 = x1 - mu, d2 = x2 - mu, d3 = x3 - mu;
                float var = qred(d0*d0 + d1*d1 + d2*d2 + d3*d3) * inv16;
                float rs = 1.f / sqrtf(var + 1e-5f);
                float n0v = d0 * rs * wv0 + bb0;
                float n1v = d1 * rs * wv1 + bb1;
                float n2v = d2 * rs * wv2 + bb2;
                float n3v = d3 * rs * wv3 + bb3;
                if (bx == 1) {
                    float ss = qred(n0v*n0v + n1v*n1v + n2v*n2v + n3v*n3v);
                    float sc = 1.f / fmaxf(sqrtf(ss), 1e-12f);
                    n0v *= sc; n1v *= sc; n2v *= sc; n3v *= sc;
                }
                int row = m0 + wm + mt * 16 + g + half * 8;
                int cb  = wn + hl * 16 + 2 * t;
                *(float2*)(dst + (size_t)row * 64 + cb)     = make_float2(n0v, n1v);
                *(float2*)(dst + (size_t)row * 64 + cb + 8) = make_float2(n2v, n3v);
            }
        }
    }
}

// ---------------------------------------------------------------------------
// Scan phaseG: group operators (T_g, U_g) by a 256-step walk.
// Grid (NSEQ, NGRP), 32 threads; thread (h, i2) owns rows i2 and i2+8.
// 32-token slabs, cp.async double-buffered.
// ---------------------------------------------------------------------------
__global__ __launch_bounds__(32) void scan_phaseG()
{
    const int n   = blockIdx.x;
    const int grp = blockIdx.y;
    const int tid = threadIdx.x;
    const int h   = tid >> 3;
    const int i2  = tid & 7;
    const int r0  = i2;
    const int r1  = i2 + 8;

    __shared__ __align__(16) float ks[2][32 * 64];
    __shared__ __align__(16) float vs[2][32 * 64];
    __shared__ __align__(16) float bs[2][128];
    __shared__ __align__(16) float as_[2][128];

    auto load_slab = [&](int s, int buf) {
        const size_t tok   = (size_t)n * TLEN + (size_t)grp * GTOK + s * 32;
        const float4* gk = (const float4*)(g_k + tok * 64);
        const float4* gv = (const float4*)(g_v + tok * 64);
#pragma unroll
        for (int e = 0; e < 16; e++) {
            CP16(su32(&((float4*)ks[buf])[tid + e * 32]), gk + tid + e * 32);
            CP16(su32(&((float4*)vs[buf])[tid + e * 32]), gv + tid + e * 32);
        }
        CP16(su32(&((float4*)bs[buf])[tid]),  (const float4*)(g_beta  + tok * 4) + tid);
        CP16(su32(&((float4*)as_[buf])[tid]), (const float4*)(g_alpha + tok * 4) + tid);
    };

    u64 Ta[8], Tb[8], Ua[8], Ub[8];
#pragma unroll
    for (int p = 0; p < 8; p++) {
        Ta[p] = pk2((2*p == r0) ? 1.f : 0.f, (2*p+1 == r0) ? 1.f : 0.f);
        Tb[p] = pk2((2*p == r1) ? 1.f : 0.f, (2*p+1 == r1) ? 1.f : 0.f);
        Ua[p] = 0ull; Ub[p] = 0ull;
    }

    load_slab(0, 0);
    CP_COMMIT();

    for (int s = 0; s < 8; s++) {
        const int cur = s & 1;
        if (s < 7) {
            load_slab(s + 1, cur ^ 1);
            CP_COMMIT();
            CP_WAIT1();
        } else {
            CP_WAIT0();
        }
        __syncwarp();

        for (int tt = 0; tt < 32; tt++) {
            const u64* kp2 = (const u64*)(ks[cur] + tt * 64 + h * 16);
            u64 k2[8];
#pragma unroll
            for (int p = 0; p < 8; p++) k2[p] = kp2[p];

            float Tka = pdot8(Ta, k2);
            float Tkb = pdot8(Tb, k2);
            float Uka = pdot8(Ua, k2);
            float Ukb = pdot8(Ub, k2);

            float a  = as_[cur][tt * HEADS + h];
            float b  = bs [cur][tt * HEADS + h];
            float va = vs [cur][tt * 64 + h * 16 + r0];
            float vb = vs [cur][tt * 64 + h * 16 + r1];
            float cTa = -a * Tka, cTb = -a * Tkb;
            float cUa = b * va - a * Uka;
            float cUb = b * vb - a * Ukb;
            u64 cTa2 = pk2(cTa, cTa), cTb2 = pk2(cTb, cTb);
            u64 cUa2 = pk2(cUa, cUa), cUb2 = pk2(cUb, cUb);

#pragma unroll
            for (int p = 0; p < 8; p++) {
                Ta[p] = ffma2(k2[p], cTa2, Ta[p]);
                Tb[p] = ffma2(k2[p], cTb2, Tb[p]);
                Ua[p] = ffma2(k2[p], cUa2, Ua[p]);
                Ub[p] = ffma2(k2[p], cUb2, Ub[p]);
            }
        }
        __syncwarp();
    }

    const size_t og = ((size_t)(n * NGRP + grp) * HEADS + h) * 256;
    u64* Td0 = (u64*)(g_GT + og + r0 * 16);
    u64* Td1 = (u64*)(g_GT + og + r1 * 16);
    u64* Ud0 = (u64*)(g_GU + og + r0 * 16);
    u64* Ud1 = (u64*)(g_GU + og + r1 * 16);
#pragma unroll
    for (int p = 0; p < 8; p++) {
        Td0[p] = Ta[p]; Td1[p] = Tb[p];
        Ud0[p] = Ua[p]; Ud1[p] = Ub[p];
    }
}

// ---------------------------------------------------------------------------
// Scan phase2b: serial over 8 group operators per n -> group start states g_G.
// ---------------------------------------------------------------------------
__global__ __launch_bounds__(64) void scan_phase2b()
{
    const int n   = blockIdx.x;
    const int tid = threadIdx.x;
    const int h   = tid >> 4;
    const int i   = tid & 15;

    __shared__ __align__(16) float Ts[HEADS * 256];
    __shared__ __align__(16) float Us[HEADS * 256];

    float Gr[16];
#pragma unroll
    for (int j = 0; j < 16; j++) Gr[j] = 0.f;

    for (int grp = 0; grp < NGRP; grp++) {
        const size_t og = (size_t)(n * NGRP + grp) * HEADS * 256;
        {
            const float4* Tg = (const float4*)(g_GT + og);
            const float4* Ug = (const float4*)(g_GU + og);
#pragma unroll
            for (int e = 0; e < 4; e++) {
                ((float4*)Ts)[tid + e * 64] = Tg[tid + e * 64];
                ((float4*)Us)[tid + e * 64] = Ug[tid + e * 64];
            }
        }
        // store group start state
        {
            float* Gd = g_G + og + (size_t)h * 256 + i * 16;
#pragma unroll
            for (int e = 0; e < 4; e++)
                *(float4*)(Gd + 4*e) = make_float4(Gr[4*e], Gr[4*e+1], Gr[4*e+2], Gr[4*e+3]);
        }
        __syncthreads();

        u64 Gn2[8];
        const u64* Uh = (const u64*)(Us + h * 256 + i * 16);
#pragma unroll
        for (int p = 0; p < 8; p++) Gn2[p] = Uh[p];
        const float* Th = Ts + h * 256;
#pragma unroll
        for (int u = 0; u < 16; u++) {
            u64 gu2 = pk2(Gr[u], Gr[u]);
            const u64* Tu = (const u64*)(Th + u * 16);
#pragma unroll
            for (int p = 0; p < 8; p++) Gn2[p] = ffma2(gu2, Tu[p], Gn2[p]);
        }
#pragma unroll
        for (int p = 0; p < 8; p++) upk2(Gn2[p], Gr[2*p], Gr[2*p+1]);
        __syncthreads();
    }
}

// ---------------------------------------------------------------------------
// Scan phase3g: replay each group of 256 tokens from g_G, emit outputs.
// Grid (NSEQ, NGRP), 32 threads; 16-token cp.async double-buffered slabs.
// ---------------------------------------------------------------------------
__global__ __launch_bounds__(32) void scan_phase3g()
{
    const int n   = blockIdx.x;
    const int grp = blockIdx.y;
    const int tid = threadIdx.x;
    const int h   = tid >> 3;
    const int i2  = tid & 7;
    const int r0  = i2;
    const int r1  = i2 + 8;

    __shared__ __align__(16) float ks[2][16 * 64];
    __shared__ __align__(16) float qs[2][16 * 64];
    __shared__ __align__(16) float vs[2][16 * 64];
    __shared__ __align__(16) float bs[2][64];
    __shared__ __align__(16) float as_[2][64];

    auto load_slab = [&](int s, int buf) {
        const size_t tok = (size_t)n * TLEN + (size_t)grp * GTOK + s * 16;
        const float4* gk = (const float4*)(g_k + tok * 64);
        const float4* gq = (const float4*)(g_q + tok * 64);
        const float4* gv = (const float4*)(g_v + tok * 64);
#pragma unroll
        for (int e = 0; e < 8; e++) {
            CP16(su32(&((float4*)ks[buf])[tid + e * 32]), gk + tid + e * 32);
            CP16(su32(&((float4*)qs[buf])[tid + e * 32]), gq + tid + e * 32);
            CP16(su32(&((float4*)vs[buf])[tid + e * 32]), gv + tid + e * 32);
        }
        if (tid < 16) {
            CP16(su32(&((float4*)bs[buf])[tid]),  (const float4*)(g_beta  + tok * 4) + tid);
            CP16(su32(&((float4*)as_[buf])[tid]), (const float4*)(g_alpha + tok * 4) + tid);
        }
    };

    // M = group start state
    u64 Ma[8], Mb[8];
    {
        const size_t og = ((size_t)(n * NGRP + grp) * HEADS + h) * 256;
        const u64* S0 = (const u64*)(g_G + og + r0 * 16);
        const u64* S1 = (const u64*)(g_G + og + r1 * 16);
#pragma unroll
        for (int p = 0; p < 8; p++) { Ma[p] = S0[p]; Mb[p] = S1[p]; }
    }

    load_slab(0, 0);
    CP_COMMIT();

    for (int s = 0; s < 16; s++) {
        const int cur = s & 1;
        if (s < 15) {
            load_slab(s + 1, cur ^ 1);
            CP_COMMIT();
            CP_WAIT1();
        } else {
            CP_WAIT0();
        }
        __syncwarp();

        const size_t tokbase = ((size_t)n * TLEN + (size_t)grp * GTOK + s * 16) * 64;
        for (int tt = 0; tt < 16; tt++) {
            const u64* kp2 = (const u64*)(ks[cur] + tt * 64 + h * 16);
            u64 k2[8];
#pragma unroll
            for (int p = 0; p < 8; p++) k2[p] = kp2[p];

            float Mka = pdot8(Ma, k2);
            float Mkb = pdot8(Mb, k2);

            float a  = as_[cur][tt * HEADS + h];
            float b  = bs [cur][tt * HEADS + h];
            float va = vs [cur][tt * 64 + h * 16 + r0];
            float vb = vs [cur][tt * 64 + h * 16 + r1];
            float ca = b * va - a * Mka;
            float cb = b * vb - a * Mkb;
            u64 ca2 = pk2(ca, ca), cb2 = pk2(cb, cb);

#pragma unroll
            for (int p = 0; p < 8; p++) {
                Ma[p] = ffma2(k2[p], ca2, Ma[p]);
                Mb[p] = ffma2(k2[p], cb2, Mb[p]);
            }

            const u64* qp2 = (const u64*)(qs[cur] + tt * 64 + h * 16);
            u64 q2[8];
#pragma unroll
            for (int p = 0; p < 8; p++) q2[p] = qp2[p];
            float oa  = pdot8(Ma, q2);
            float ob_ = pdot8(Mb, q2);

            g_o[tokbase + tt * 64 + h * 16 + r0] = oa;
            g_o[tokbase + tt * 64 + h * 16 + r1] = ob_;
        }
        __syncwarp();
    }
}

// ---------------------------------------------------------------------------
// Kernel D (tf32, cp.async 2-stage, BK=16): fib = o @ out_w^T + out_b,
// scatter to (B,T,P,K).
// ---------------------------------------------------------------------------
__global__ __launch_bounds__(128) void gemmD_kernel(const float* __restrict__ ob,
                                                    float* __restrict__ out)
{
    __shared__ __align__(16) float As[2][128][A_KS];
    __shared__ __align__(16) float Bs[2][16][B_KS];

    const int tid  = threadIdx.x;
    const int lane = tid & 31;
    const int wid  = tid >> 5;
    const int g    = lane >> 2;
    const int t    = lane & 3;
    const int wm   = (wid >> 1) * 64;
    const int wn   = (wid & 1) * 32;
    const int m0   = blockIdx.y * 128;
    const int n0   = blockIdx.x * 64;

    float acc[4][4][4];
#pragma unroll
    for (int i = 0; i < 4; i++)
#pragma unroll
        for (int j = 0; j < 4; j++)
#pragma unroll
            for (int r = 0; r < 4; r++) acc[i][j][r] = 0.f;

    auto load_tiles = [&](int k0, int buf) {
#pragma unroll
        for (int i = 0; i < 4; i++) {
            int e   = i * 128 + tid;
            int row = e >> 2;
            int cq  = (e & 3) * 4;
            CP16(su32(&As[buf][row][cq]),
                 g_o + (size_t)(m0 + row) * 64 + k0 + cq);
        }
#pragma unroll
        for (int i = 0; i < 2; i++) {
            int e  = i * 128 + tid;
            int kk = e >> 4;
            int cq = (e & 15) * 4;
            CP16(su32(&Bs[buf][kk][cq]),
                 g_Bpack2 + (size_t)(k0 + kk) * KOUT + n0 + cq);
        }
    };

    load_tiles(0, 0);
    CP_COMMIT();

    for (int kt = 0; kt < 4; kt++) {
        const int cur = kt & 1;
        if (kt < 3) {
            load_tiles((kt + 1) * 16, cur ^ 1);
            CP_COMMIT();
            CP_WAIT1();
        } else {
            CP_WAIT0();
        }
        __syncthreads();

#pragma unroll
        for (int ks = 0; ks < 2; ks++) {
            const int kb = ks * 8;
            unsigned a[4][4], b[4][2];
#pragma unroll
            for (int mt = 0; mt < 4; mt++) {
                int r = wm + mt * 16 + g;
                a[mt][0] = futf(As[cur][r][kb + t]);
                a[mt][1] = futf(As[cur][r + 8][kb + t]);
                a[mt][2] = futf(As[cur][r][kb + t + 4]);
                a[mt][3] = futf(As[cur][r + 8][kb + t + 4]);
            }
#pragma unroll
            for (int nt = 0; nt < 4; nt++) {
                int n = wn + nt * 8 + g;
                b[nt][0] = fu(Bs[cur][kb + t][n]);
                b[nt][1] = fu(Bs[cur][kb + t + 4][n]);
            }
#pragma unroll
            for (int mt = 0; mt < 4; mt++)
#pragma unroll
                for (int nt = 0; nt < 4; nt++)
                    MMA_TF32(acc[mt][nt], a[mt], b[nt]);
        }
        __syncthreads();
    }

    const int nseq = m0 >> 11;
    const int tb   = m0 & 2047;
    const int bb   = nseq >> 4;
    const int pp   = nseq & 15;
#pragma unroll
    for (int mt = 0; mt < 4; mt++) {
#pragma unroll
        for (int nt = 0; nt < 4; nt++) {
            int r   = wm + mt * 16 + g;
            int col = n0 + wn + nt * 8 + 2 * t;
            float b0 = ob[col], b1 = ob[col + 1];
            int t1 = tb + r;
            size_t d1 = (((size_t)bb * TLEN + t1) * 16 + pp) * KOUT + col;
            *(float2*)(out + d1) = make_float2(acc[mt][nt][0] + b0,
                                               acc[mt][nt][1] + b1);
            int t2 = t1 + 8;
            size_t d2 = (((size_t)bb * TLEN + t2) * 16 + pp) * KOUT + col;
            *(float2*)(out + d2) = make_float2(acc[mt][nt][2] + b0,
                                               acc[mt][nt][3] + b1);
        }
    }
}

// ---------------------------------------------------------------------------
// launch
// ---------------------------------------------------------------------------
extern "C" void kernel_launch(void* const* d_in, const int* in_sizes, int n_in,
                              void* d_out, int out_size)
{
    const float* joint = (const float*)d_in[0];
    const float* curv  = (const float*)d_in[1];
    const float* ent   = (const float*)d_in[2];
    const float* Wq    = (const float*)d_in[3];
    const float* Wk    = (const float*)d_in[4];
    const float* Wv    = (const float*)d_in[5];
    const float* Wbw   = (const float*)d_in[6];
    const float* Wbb   = (const float*)d_in[7];
    const float* Waw   = (const float*)d_in[8];
    const float* Wab   = (const float*)d_in[9];
    const float* cw    = (const float*)d_in[10];
    const float* ew    = (const float*)d_in[11];
    const float* out_w = (const float*)d_in[12];
    const float* out_b = (const float*)d_in[13];
    const float* lqw   = (const float*)d_in[14];
    const float* lqb   = (const float*)d_in[15];
    const float* lkw   = (const float*)d_in[16];
    const float* lkb   = (const float*)d_in[17];
    float* out = (float*)d_out;

    pack_kernel<<<256, 256>>>(Wq, Wk, Wv, out_w, Wbw, Waw);

    gemmA_kernel<<<dim3(3, M_TOK / 128), 128>>>(joint, lqw, lqb, lkw, lkb,
                                                curv, ent, Wbb, Wab, cw, ew);

    scan_phaseG<<<dim3(NSEQ, NGRP), 32>>>();
    scan_phase2b<<<NSEQ, 64>>>();
    scan_phase3g<<<dim3(NSEQ, NGRP), 32>>>();

    gemmD_kernel<<<dim3(KOUT / 64, M_TOK / 128), 128>>>(out_b, out);
}